// round 1
// baseline (speedup 1.0000x reference)
#include <cuda_runtime.h>
#include <math_constants.h>

#define DIMC   1024
#define NHEAD  16
#define HD     64
#define BATCH  2
#define SEQ    2048
#define MTOT   (BATCH*SEQ)          // 4096
#define QKVN   (3*DIMC)             // 3072

// log2(10000)
#define LOG2_BASE 13.287712379549449f

// Scratch (allocation-free rule: device globals)
__device__ float g_Q[BATCH*NHEAD*SEQ*HD];
__device__ float g_K[BATCH*NHEAD*SEQ*HD];
__device__ float g_V[BATCH*NHEAD*SEQ*HD];
__device__ float g_O[BATCH*SEQ*DIMC];

// ---------------------------------------------------------------------------
// SGEMM core: C[M x Ncols] = A[M x 1024] @ W[Ncols x 1024]^T + bias
// BM=BN=128, BK=8, 16x16 threads, 8x8 micro-tile per thread.
// QKV=true: epilogue applies bias + RoPE and scatters into g_Q/g_K/g_V.
// QKV=false: A := g_O, epilogue adds bias and writes C.
// ---------------------------------------------------------------------------
template<bool QKV>
__global__ __launch_bounds__(256)
void gemm_kernel(const float* __restrict__ A_in,
                 const float* __restrict__ W,
                 const float* __restrict__ bias,
                 float* __restrict__ C)
{
    __shared__ float As[8][128];
    __shared__ float Bs[8][128];

    const int tx  = threadIdx.x;          // 0..15
    const int ty  = threadIdx.y;          // 0..15
    const int tid = ty * 16 + tx;
    const int row0 = blockIdx.y * 128;
    const int col0 = blockIdx.x * 128;

    const float* A = QKV ? A_in : g_O;

    // Load mapping: each thread fetches one float4 of A and one of W per k-step.
    const int lr = tid >> 1;              // 0..127 row within tile
    const int lk = (tid & 1) * 4;         // 0 or 4 within BK

    const float* Ag = A + (size_t)(row0 + lr) * DIMC + lk;
    const float* Wg = W + (size_t)(col0 + lr) * DIMC + lk;

    float acc[8][8];
#pragma unroll
    for (int i = 0; i < 8; i++)
#pragma unroll
        for (int j = 0; j < 8; j++) acc[i][j] = 0.f;

    for (int k0 = 0; k0 < DIMC; k0 += 8) {
        float4 av = *(const float4*)(Ag + k0);
        float4 wv = *(const float4*)(Wg + k0);
        As[lk + 0][lr] = av.x; As[lk + 1][lr] = av.y;
        As[lk + 2][lr] = av.z; As[lk + 3][lr] = av.w;
        Bs[lk + 0][lr] = wv.x; Bs[lk + 1][lr] = wv.y;
        Bs[lk + 2][lr] = wv.z; Bs[lk + 3][lr] = wv.w;
        __syncthreads();

#pragma unroll
        for (int k = 0; k < 8; k++) {
            float4 a0 = *(const float4*)&As[k][ty * 8];
            float4 a1 = *(const float4*)&As[k][ty * 8 + 4];
            float4 b0 = *(const float4*)&Bs[k][tx * 8];
            float4 b1 = *(const float4*)&Bs[k][tx * 8 + 4];
            float ar[8] = {a0.x, a0.y, a0.z, a0.w, a1.x, a1.y, a1.z, a1.w};
            float br[8] = {b0.x, b0.y, b0.z, b0.w, b1.x, b1.y, b1.z, b1.w};
#pragma unroll
            for (int i = 0; i < 8; i++)
#pragma unroll
                for (int j = 0; j < 8; j++)
                    acc[i][j] = fmaf(ar[i], br[j], acc[i][j]);
        }
        __syncthreads();
    }

    // ------------------------- epilogue -------------------------
    const int jbase = col0 + tx * 8;

    if (QKV) {
        // Block's 128-col span never crosses the q/k/v boundaries (multiples of 1024).
        const bool is_v = (jbase >= 2 * DIMC);
        const bool is_q = (jbase < DIMC);
        const int  local = is_v ? (jbase - 2 * DIMC) : (jbase & (DIMC - 1));
        const int  h  = local >> 6;
        const int  d0 = local & 63;

        float bvals[8];
#pragma unroll
        for (int jj = 0; jj < 8; jj++) bvals[jj] = bias[jbase + jj];

#pragma unroll
        for (int i = 0; i < 8; i++) {
            const int m = row0 + ty * 8 + i;
            const int b = m >> 11;            // /2048
            const int n = m & 2047;
            float* dst = (is_v ? g_V : (is_q ? g_Q : g_K))
                         + ((size_t)(b * NHEAD + h) * SEQ + n) * HD + d0;
            if (is_v) {
#pragma unroll
                for (int jj = 0; jj < 8; jj++)
                    dst[jj] = acc[i][jj] + bvals[jj];
            } else {
                const float fn = (float)n;
#pragma unroll
                for (int jj = 0; jj < 8; jj += 2) {
                    const int d = d0 + jj;                   // even
                    float inv = exp2f(-(float)d * (LOG2_BASE / 64.0f));
                    float sv, cv;
                    sincosf(fn * inv, &sv, &cv);
                    float e = acc[i][jj]     + bvals[jj];
                    float o = acc[i][jj + 1] + bvals[jj + 1];
                    float eo = e * cv - o * sv;
                    float oo = e * sv + o * cv;
                    if (is_q) { eo *= 0.125f; oo *= 0.125f; } // fold 1/sqrt(64)
                    dst[jj]     = eo;
                    dst[jj + 1] = oo;
                }
            }
        }
    } else {
#pragma unroll
        for (int i = 0; i < 8; i++) {
            const int m = row0 + ty * 8 + i;
            float* dst = C + (size_t)m * DIMC + jbase;
#pragma unroll
            for (int jj = 0; jj < 8; jj += 4) {
                float4 v;
                v.x = acc[i][jj + 0] + bias[jbase + jj + 0];
                v.y = acc[i][jj + 1] + bias[jbase + jj + 1];
                v.z = acc[i][jj + 2] + bias[jbase + jj + 2];
                v.w = acc[i][jj + 3] + bias[jbase + jj + 3];
                *(float4*)(dst + jj) = v;
            }
        }
    }
}

// ---------------------------------------------------------------------------
// Flash attention: block = (q-tile of 64, one (b,h)). 256 threads.
// Qs[r][d], Kst[d][c] (K transposed; reused as P[r][c]), Vs[c][d].
// Online softmax with warp-shuffle row reductions (row = 16-lane group).
// ---------------------------------------------------------------------------
__global__ __launch_bounds__(256)
void attn_kernel()
{
    __shared__ float Qs [64][64];
    __shared__ float Kst[64][64];   // also P buffer
    __shared__ float Vs [64][64];

    const int tid = threadIdx.x;
    const int tx  = tid & 15;       // col group
    const int ty  = tid >> 4;       // row group
    const int bh  = blockIdx.y;     // 0..31
    const int n0  = blockIdx.x * 64;

    const size_t base = (size_t)bh * SEQ * HD;
    const float* Qg = g_Q + base;
    const float* Kg = g_K + base;
    const float* Vg = g_V + base;

    // Load Q tile (64x64) with float4s
    for (int t = tid; t < 64 * 16; t += 256) {
        int r = t >> 4, c4 = t & 15;
        *(float4*)&Qs[r][c4 * 4] = *(const float4*)(Qg + (size_t)(n0 + r) * HD + c4 * 4);
    }

    float m_prev[4], l_prev[4], o_acc[4][4];
#pragma unroll
    for (int i = 0; i < 4; i++) {
        m_prev[i] = -CUDART_INF_F;
        l_prev[i] = 0.f;
#pragma unroll
        for (int j = 0; j < 4; j++) o_acc[i][j] = 0.f;
    }

    for (int kt = 0; kt < SEQ / 64; kt++) {
        __syncthreads();   // protect Kst(P)/Vs from previous iteration (and Qs on iter 0)
        const int k0 = kt * 64;
        for (int t = tid; t < 64 * 16; t += 256) {
            int r = t >> 4, c4 = t & 15;
            float4 kv = *(const float4*)(Kg + (size_t)(k0 + r) * HD + c4 * 4);
            Kst[c4 * 4 + 0][r] = kv.x;
            Kst[c4 * 4 + 1][r] = kv.y;
            Kst[c4 * 4 + 2][r] = kv.z;
            Kst[c4 * 4 + 3][r] = kv.w;
            *(float4*)&Vs[r][c4 * 4] = *(const float4*)(Vg + (size_t)(k0 + r) * HD + c4 * 4);
        }
        __syncthreads();

        // S = Q @ K^T  (4x4 per thread)
        float s[4][4];
#pragma unroll
        for (int i = 0; i < 4; i++)
#pragma unroll
            for (int j = 0; j < 4; j++) s[i][j] = 0.f;

        for (int d = 0; d < 64; d += 4) {
            float qf[4][4];
#pragma unroll
            for (int i = 0; i < 4; i++) {
                float4 q4 = *(const float4*)&Qs[ty * 4 + i][d];
                qf[i][0] = q4.x; qf[i][1] = q4.y; qf[i][2] = q4.z; qf[i][3] = q4.w;
            }
#pragma unroll
            for (int dd = 0; dd < 4; dd++) {
                float4 kb = *(const float4*)&Kst[d + dd][tx * 4];
#pragma unroll
                for (int i = 0; i < 4; i++) {
                    s[i][0] = fmaf(qf[i][dd], kb.x, s[i][0]);
                    s[i][1] = fmaf(qf[i][dd], kb.y, s[i][1]);
                    s[i][2] = fmaf(qf[i][dd], kb.z, s[i][2]);
                    s[i][3] = fmaf(qf[i][dd], kb.w, s[i][3]);
                }
            }
        }

        // Online softmax per row (16 lanes own a row; shuffle-reduce)
#pragma unroll
        for (int i = 0; i < 4; i++) {
            float mx = fmaxf(fmaxf(s[i][0], s[i][1]), fmaxf(s[i][2], s[i][3]));
#pragma unroll
            for (int off = 8; off >= 1; off >>= 1)
                mx = fmaxf(mx, __shfl_xor_sync(0xffffffffu, mx, off));
            float m_new = fmaxf(m_prev[i], mx);
            float alpha = __expf(m_prev[i] - m_new);
            float lsum = 0.f;
#pragma unroll
            for (int j = 0; j < 4; j++) {
                s[i][j] = __expf(s[i][j] - m_new);
                lsum += s[i][j];
            }
#pragma unroll
            for (int off = 8; off >= 1; off >>= 1)
                lsum += __shfl_xor_sync(0xffffffffu, lsum, off);
            l_prev[i] = l_prev[i] * alpha + lsum;
            m_prev[i] = m_new;
#pragma unroll
            for (int j = 0; j < 4; j++) o_acc[i][j] *= alpha;
        }

        __syncthreads();   // all lanes done reading Kst as K
        // Write P into Kst buffer as P[r][c]
#pragma unroll
        for (int i = 0; i < 4; i++)
            *(float4*)&Kst[ty * 4 + i][tx * 4] =
                make_float4(s[i][0], s[i][1], s[i][2], s[i][3]);
        __syncthreads();

        // O += P @ V
        for (int c = 0; c < 64; c += 4) {
            float pf[4][4];
#pragma unroll
            for (int i = 0; i < 4; i++) {
                float4 p4 = *(const float4*)&Kst[ty * 4 + i][c];
                pf[i][0] = p4.x; pf[i][1] = p4.y; pf[i][2] = p4.z; pf[i][3] = p4.w;
            }
#pragma unroll
            for (int cc = 0; cc < 4; cc++) {
                float4 vb = *(const float4*)&Vs[c + cc][tx * 4];
#pragma unroll
                for (int i = 0; i < 4; i++) {
                    o_acc[i][0] = fmaf(pf[i][cc], vb.x, o_acc[i][0]);
                    o_acc[i][1] = fmaf(pf[i][cc], vb.y, o_acc[i][1]);
                    o_acc[i][2] = fmaf(pf[i][cc], vb.z, o_acc[i][2]);
                    o_acc[i][3] = fmaf(pf[i][cc], vb.w, o_acc[i][3]);
                }
            }
        }
    }

    // Normalize and write to g_O in [B, N, H*D] layout
    const int b = bh >> 4;
    const int h = bh & 15;
#pragma unroll
    for (int i = 0; i < 4; i++) {
        const int n = n0 + ty * 4 + i;
        const float il = 1.f / l_prev[i];
        float4 ov = make_float4(o_acc[i][0] * il, o_acc[i][1] * il,
                                o_acc[i][2] * il, o_acc[i][3] * il);
        *(float4*)&g_O[((size_t)(b * SEQ + n)) * DIMC + h * HD + tx * 4] = ov;
    }
}

// ---------------------------------------------------------------------------

extern "C" void kernel_launch(void* const* d_in, const int* in_sizes, int n_in,
                              void* d_out, int out_size)
{
    const float* x      = (const float*)d_in[0];
    const float* qkv_w  = (const float*)d_in[1];
    const float* qkv_b  = (const float*)d_in[2];
    const float* proj_w = (const float*)d_in[3];
    const float* proj_b = (const float*)d_in[4];
    float* out = (float*)d_out;

    dim3 blk(16, 16);
    gemm_kernel<true ><<<dim3(QKVN / 128, MTOT / 128), blk>>>(x, qkv_w, qkv_b, nullptr);
    attn_kernel<<<dim3(SEQ / 64, BATCH * NHEAD), 256>>>();
    gemm_kernel<false><<<dim3(DIMC / 128, MTOT / 128), blk>>>(nullptr, proj_w, proj_b, out);
}

// round 7
// speedup vs baseline: 1.1399x; 1.1399x over previous
// Round 7 submission — functionally identical to the round-6 design (infra
// failure prevented benching). SIMT-only instruction set proven safe in R1.
#include <cuda_runtime.h>
#include <math_constants.h>

#define DIMC   1024
#define NHEAD  16
#define HD     64
#define BATCH  2
#define SEQ    2048
#define MTOT   (BATCH*SEQ)          // 4096
#define QKVN   (3*DIMC)             // 3072
#define LOG2_BASE 13.287712379549449f

// Scratch (allocation-free rule: device globals) — identical to round-1 footprint
__device__ float g_Q[BATCH*NHEAD*SEQ*HD];
__device__ float g_K[BATCH*NHEAD*SEQ*HD];
__device__ float g_V[BATCH*NHEAD*SEQ*HD];
__device__ float g_O[MTOT*DIMC];

// ---------------------------------------------------------------------------
// SGEMM: C[M x N] = A[M x 1024] @ W[N x 1024]^T + bias
// BM=BN=128, BK=16, 256 threads, 8x8 micro-tile, double-buffered smem with
// register prefetch -> ONE __syncthreads per k-tile.
// QKV=true: epilogue applies bias + RoPE, scatters into g_Q/g_K/g_V.
// QKV=false: A := g_O, epilogue adds bias, writes C.
// ---------------------------------------------------------------------------
template<bool QKV>
__global__ __launch_bounds__(256)
void gemm_kernel(const float* __restrict__ A_in,
                 const float* __restrict__ W,
                 const float* __restrict__ bias,
                 float* __restrict__ C)
{
    __shared__ float As[2][16][128];
    __shared__ float Bs[2][16][128];

    const int tid = threadIdx.x;
    const int tx  = tid & 15;
    const int ty  = tid >> 4;
    const int row0 = blockIdx.y * 128;
    const int col0 = blockIdx.x * 128;

    const float* A = QKV ? A_in : g_O;

    // loader: each thread owns one row (of A and of W) and 8 of the 16 k's
    const int lr = tid >> 1;              // 0..127
    const int lk = (tid & 1) * 8;         // 0 or 8

    const float* Ag = A + (size_t)(row0 + lr) * DIMC + lk;
    const float* Wg = W + (size_t)(col0 + lr) * DIMC + lk;

    float acc[8][8];
#pragma unroll
    for (int i = 0; i < 8; i++)
#pragma unroll
        for (int j = 0; j < 8; j++) acc[i][j] = 0.f;

    // prefetch k-tile 0
    float4 a0 = *(const float4*)(Ag);
    float4 a1 = *(const float4*)(Ag + 4);
    float4 w0 = *(const float4*)(Wg);
    float4 w1 = *(const float4*)(Wg + 4);

    const int NK = DIMC / 16;   // 64
#pragma unroll 1
    for (int it = 0; it < NK; it++) {
        const int buf = it & 1;
        // store current tile (transposed: [k][row])
        As[buf][lk+0][lr] = a0.x; As[buf][lk+1][lr] = a0.y;
        As[buf][lk+2][lr] = a0.z; As[buf][lk+3][lr] = a0.w;
        As[buf][lk+4][lr] = a1.x; As[buf][lk+5][lr] = a1.y;
        As[buf][lk+6][lr] = a1.z; As[buf][lk+7][lr] = a1.w;
        Bs[buf][lk+0][lr] = w0.x; Bs[buf][lk+1][lr] = w0.y;
        Bs[buf][lk+2][lr] = w0.z; Bs[buf][lk+3][lr] = w0.w;
        Bs[buf][lk+4][lr] = w1.x; Bs[buf][lk+5][lr] = w1.y;
        Bs[buf][lk+6][lr] = w1.z; Bs[buf][lk+7][lr] = w1.w;
        __syncthreads();

        if (it + 1 < NK) {
            const int k0 = (it + 1) * 16;
            a0 = *(const float4*)(Ag + k0);
            a1 = *(const float4*)(Ag + k0 + 4);
            w0 = *(const float4*)(Wg + k0);
            w1 = *(const float4*)(Wg + k0 + 4);
        }

#pragma unroll
        for (int k = 0; k < 16; k++) {
            float4 x0 = *(const float4*)&As[buf][k][ty * 8];
            float4 x1 = *(const float4*)&As[buf][k][ty * 8 + 4];
            float4 y0 = *(const float4*)&Bs[buf][k][tx * 8];
            float4 y1 = *(const float4*)&Bs[buf][k][tx * 8 + 4];
            float ar[8] = {x0.x, x0.y, x0.z, x0.w, x1.x, x1.y, x1.z, x1.w};
            float br[8] = {y0.x, y0.y, y0.z, y0.w, y1.x, y1.y, y1.z, y1.w};
#pragma unroll
            for (int i = 0; i < 8; i++)
#pragma unroll
                for (int j = 0; j < 8; j++)
                    acc[i][j] = fmaf(ar[i], br[j], acc[i][j]);
        }
        // next iteration stores into the other buffer: no second sync needed
    }

    // ------------------------- epilogue (round-1-proven) -------------------------
    const int jbase = col0 + tx * 8;

    if (QKV) {
        const bool is_v = (jbase >= 2 * DIMC);
        const bool is_q = (jbase < DIMC);
        const int  local = is_v ? (jbase - 2 * DIMC) : (jbase & (DIMC - 1));
        const int  h  = local >> 6;
        const int  d0 = local & 63;

        float bvals[8];
#pragma unroll
        for (int jj = 0; jj < 8; jj++) bvals[jj] = bias[jbase + jj];

#pragma unroll
        for (int i = 0; i < 8; i++) {
            const int m = row0 + ty * 8 + i;
            const int b = m >> 11;            // /2048
            const int n = m & 2047;
            float* dst = (is_v ? g_V : (is_q ? g_Q : g_K))
                         + ((size_t)(b * NHEAD + h) * SEQ + n) * HD + d0;
            if (is_v) {
#pragma unroll
                for (int jj = 0; jj < 8; jj++)
                    dst[jj] = acc[i][jj] + bvals[jj];
            } else {
                const float fn = (float)n;
#pragma unroll
                for (int jj = 0; jj < 8; jj += 2) {
                    const int d = d0 + jj;                   // even
                    float inv = exp2f(-(float)d * (LOG2_BASE / 64.0f));
                    float sv, cv;
                    sincosf(fn * inv, &sv, &cv);
                    float e = acc[i][jj]     + bvals[jj];
                    float o = acc[i][jj + 1] + bvals[jj + 1];
                    float eo = e * cv - o * sv;
                    float oo = e * sv + o * cv;
                    if (is_q) { eo *= 0.125f; oo *= 0.125f; } // fold 1/sqrt(64)
                    dst[jj]     = eo;
                    dst[jj + 1] = oo;
                }
            }
        }
    } else {
#pragma unroll
        for (int i = 0; i < 8; i++) {
            const int m = row0 + ty * 8 + i;
            float* dst = C + (size_t)m * DIMC + jbase;
#pragma unroll
            for (int jj = 0; jj < 8; jj += 4) {
                float4 v;
                v.x = acc[i][jj + 0] + bias[jbase + jj + 0];
                v.y = acc[i][jj + 1] + bias[jbase + jj + 1];
                v.z = acc[i][jj + 2] + bias[jbase + jj + 2];
                v.w = acc[i][jj + 3] + bias[jbase + jj + 3];
                *(float4*)(dst + jj) = v;
            }
        }
    }
}

// ---------------------------------------------------------------------------
// Flash attention: block = (64 q-rows, one (b,h)), 128 threads.
// Same layouts/strides/softmax scheme as round 1, but 8x4 micro-tile per
// thread (ty 0..7 owns 8 rows; tx 0..15 owns 4 cols) -> 2x FMA per LDS.
// Qs[r][d], Kst[d][c] (K transposed; reused as P[r][c]), Vs[c][d]. 48KB smem.
// ---------------------------------------------------------------------------
__global__ __launch_bounds__(128)
void attn_kernel()
{
    __shared__ float Qs [64][64];
    __shared__ float Kst[64][64];   // also P buffer
    __shared__ float Vs [64][64];

    const int tid = threadIdx.x;
    const int tx  = tid & 15;       // col group
    const int ty  = tid >> 4;       // row group (0..7)
    const int bh  = blockIdx.y;     // 0..31
    const int n0  = blockIdx.x * 64;

    const size_t base = (size_t)bh * SEQ * HD;
    const float* Qg = g_Q + base;
    const float* Kg = g_K + base;
    const float* Vg = g_V + base;

    // Load Q tile (64x64) with float4s
    for (int t = tid; t < 64 * 16; t += 128) {
        int r = t >> 4, c4 = t & 15;
        *(float4*)&Qs[r][c4 * 4] = *(const float4*)(Qg + (size_t)(n0 + r) * HD + c4 * 4);
    }

    float m_prev[8], l_prev[8], o_acc[8][4];
#pragma unroll
    for (int i = 0; i < 8; i++) {
        m_prev[i] = -CUDART_INF_F;
        l_prev[i] = 0.f;
#pragma unroll
        for (int j = 0; j < 4; j++) o_acc[i][j] = 0.f;
    }

#pragma unroll 1
    for (int kt = 0; kt < SEQ / 64; kt++) {
        __syncthreads();   // protect Kst(P)/Vs from previous iteration (and Qs on iter 0)
        const int k0 = kt * 64;
        for (int t = tid; t < 64 * 16; t += 128) {
            int r = t >> 4, c4 = t & 15;
            float4 kv = *(const float4*)(Kg + (size_t)(k0 + r) * HD + c4 * 4);
            Kst[c4 * 4 + 0][r] = kv.x;
            Kst[c4 * 4 + 1][r] = kv.y;
            Kst[c4 * 4 + 2][r] = kv.z;
            Kst[c4 * 4 + 3][r] = kv.w;
            *(float4*)&Vs[r][c4 * 4] = *(const float4*)(Vg + (size_t)(k0 + r) * HD + c4 * 4);
        }
        __syncthreads();

        // S = Q @ K^T  (8x4 per thread)
        float s[8][4];
#pragma unroll
        for (int i = 0; i < 8; i++)
#pragma unroll
            for (int j = 0; j < 4; j++) s[i][j] = 0.f;

#pragma unroll 1
        for (int d = 0; d < 64; d += 4) {
            float qf[8][4];
#pragma unroll
            for (int i = 0; i < 8; i++) {
                float4 q4 = *(const float4*)&Qs[ty * 8 + i][d];
                qf[i][0] = q4.x; qf[i][1] = q4.y; qf[i][2] = q4.z; qf[i][3] = q4.w;
            }
#pragma unroll
            for (int dd = 0; dd < 4; dd++) {
                float4 kb = *(const float4*)&Kst[d + dd][tx * 4];
#pragma unroll
                for (int i = 0; i < 8; i++) {
                    s[i][0] = fmaf(qf[i][dd], kb.x, s[i][0]);
                    s[i][1] = fmaf(qf[i][dd], kb.y, s[i][1]);
                    s[i][2] = fmaf(qf[i][dd], kb.z, s[i][2]);
                    s[i][3] = fmaf(qf[i][dd], kb.w, s[i][3]);
                }
            }
        }

        // Online softmax per row (16 lanes own a row; shuffle-reduce)
#pragma unroll
        for (int i = 0; i < 8; i++) {
            float mx = fmaxf(fmaxf(s[i][0], s[i][1]), fmaxf(s[i][2], s[i][3]));
#pragma unroll
            for (int off = 8; off >= 1; off >>= 1)
                mx = fmaxf(mx, __shfl_xor_sync(0xffffffffu, mx, off));
            float m_new = fmaxf(m_prev[i], mx);
            float alpha = __expf(m_prev[i] - m_new);
            float lsum = 0.f;
#pragma unroll
            for (int j = 0; j < 4; j++) {
                s[i][j] = __expf(s[i][j] - m_new);
                lsum += s[i][j];
            }
#pragma unroll
            for (int off = 8; off >= 1; off >>= 1)
                lsum += __shfl_xor_sync(0xffffffffu, lsum, off);
            l_prev[i] = l_prev[i] * alpha + lsum;
            m_prev[i] = m_new;
#pragma unroll
            for (int j = 0; j < 4; j++) o_acc[i][j] *= alpha;
        }

        __syncthreads();   // all lanes done reading Kst as K
        // Write P into Kst buffer as P[r][c]
#pragma unroll
        for (int i = 0; i < 8; i++)
            *(float4*)&Kst[ty * 8 + i][tx * 4] =
                make_float4(s[i][0], s[i][1], s[i][2], s[i][3]);
        __syncthreads();

        // O += P @ V
#pragma unroll 1
        for (int c = 0; c < 64; c += 4) {
            float pf[8][4];
#pragma unroll
            for (int i = 0; i < 8; i++) {
                float4 p4 = *(const float4*)&Kst[ty * 8 + i][c];
                pf[i][0] = p4.x; pf[i][1] = p4.y; pf[i][2] = p4.z; pf[i][3] = p4.w;
            }
#pragma unroll
            for (int cc = 0; cc < 4; cc++) {
                float4 vb = *(const float4*)&Vs[c + cc][tx * 4];
#pragma unroll
                for (int i = 0; i < 8; i++) {
                    o_acc[i][0] = fmaf(pf[i][cc], vb.x, o_acc[i][0]);
                    o_acc[i][1] = fmaf(pf[i][cc], vb.y, o_acc[i][1]);
                    o_acc[i][2] = fmaf(pf[i][cc], vb.z, o_acc[i][2]);
                    o_acc[i][3] = fmaf(pf[i][cc], vb.w, o_acc[i][3]);
                }
            }
        }
    }

    // Normalize and write to g_O in [B, N, H*D] layout
    const int b = bh >> 4;
    const int h = bh & 15;
#pragma unroll
    for (int i = 0; i < 8; i++) {
        const int n = n0 + ty * 8 + i;
        const float il = 1.f / l_prev[i];
        float4 ov = make_float4(o_acc[i][0] * il, o_acc[i][1] * il,
                                o_acc[i][2] * il, o_acc[i][3] * il);
        *(float4*)&g_O[((size_t)(b * SEQ + n)) * DIMC + h * HD + tx * 4] = ov;
    }
}

// ---------------------------------------------------------------------------

extern "C" void kernel_launch(void* const* d_in, const int* in_sizes, int n_in,
                              void* d_out, int out_size)
{
    const float* x      = (const float*)d_in[0];
    const float* qkv_w  = (const float*)d_in[1];
    const float* qkv_b  = (const float*)d_in[2];
    const float* proj_w = (const float*)d_in[3];
    const float* proj_b = (const float*)d_in[4];
    float* out = (float*)d_out;

    gemm_kernel<true ><<<dim3(QKVN / 128, MTOT / 128), 256>>>(x, qkv_w, qkv_b, nullptr);
    attn_kernel<<<dim3(SEQ / 64, BATCH * NHEAD), 128>>>();
    gemm_kernel<false><<<dim3(DIMC / 128, MTOT / 128), 256>>>(nullptr, proj_w, proj_b, out);
}

// round 8
// speedup vs baseline: 2.4798x; 2.1755x over previous
// TF32 mma.sync pipeline, array-free (named scalars only) to guarantee a
// zero-byte stack frame — hypothesis: the fixed 128MiB guard trips were a
// lazily-allocated lmem pool from kernels with nonzero stack.
#include <cuda_runtime.h>
#include <math_constants.h>

#define DIMC   1024
#define NHEAD  16
#define HD     64
#define BATCH  2
#define SEQ    2048
#define MTOT   (BATCH*SEQ)          // 4096
#define QKVN   (3*DIMC)             // 3072
#define LOG2_BASE 13.287712379549449f

// ---- device-global scratch: exactly the round-1/7-proven 64 MiB ----
__device__ float g_Q[BATCH*NHEAD*SEQ*HD];     // [bh][n][d]
__device__ float g_K[BATCH*NHEAD*SEQ*HD];     // [bh][n][d]
__device__ float g_V[BATCH*NHEAD*SEQ*HD];     // [bh][n][d]
__device__ float g_O[MTOT*DIMC];              // [m][1024]

// RNE round-to-tf32 in pure integer math (no asm)
__device__ __forceinline__ float tf32r(float x) {
    unsigned u = __float_as_uint(x);
    u = (u + 0x0FFFu + ((u >> 13) & 1u)) & 0xFFFFE000u;
    return __uint_as_float(u);
}

// m16n8k8 tf32 mma: D += A*B. All operands individual scalars.
#define MMA(d0,d1,d2,d3, a0,a1,a2,a3, b0,b1)                                   \
    asm volatile("mma.sync.aligned.m16n8k8.row.col.f32.tf32.tf32.f32 "         \
                 "{%0,%1,%2,%3},{%4,%5,%6,%7},{%8,%9},{%0,%1,%2,%3};"          \
                 : "+f"(d0), "+f"(d1), "+f"(d2), "+f"(d3)                      \
                 : "r"(__float_as_uint(a0)), "r"(__float_as_uint(a1)),         \
                   "r"(__float_as_uint(a2)), "r"(__float_as_uint(a3)),         \
                   "r"(__float_as_uint(b0)), "r"(__float_as_uint(b1)))

// ---------------------------------------------------------------------------
// TF32 GEMM: C[M,N] = A[M,1024] @ W[N,1024]^T (+bias; +RoPE for MODE 0)
// BM=128, BN=64, BK=16. 8 warps as 4(m) x 2(n); warp tile 32x32.
// Fragment loads are scalar LDS from padded (stride-20) smem: per-fragment
// bank pattern (4r+c mod 32) is conflict-free. One __syncthreads per k-tile.
// ---------------------------------------------------------------------------
template<int MODE>   // 0 = QKV (+bias+RoPE, scatter to g_Q/g_K/g_V), 1 = proj
__global__ __launch_bounds__(256)
void tgemm(const float* __restrict__ A_in, const float* __restrict__ W,
           const float* __restrict__ bias, float* __restrict__ C)
{
    __shared__ float As[2][128 * 20];
    __shared__ float Ws[2][64 * 20];

    const int tid  = threadIdx.x;
    const int lane = tid & 31;
    const int w    = tid >> 5;
    const int wm   = w & 3;          // 0..3 (M)
    const int wn   = w >> 2;         // 0..1 (N)
    const int row0 = blockIdx.y * 128;
    const int col0 = blockIdx.x * 64;

    const float* A = (MODE == 0) ? A_in : g_O;

    // loaders
    const int alr = tid >> 1;            // 0..127
    const int alk = (tid & 1) * 8;       // 0 or 8
    const int wlr = tid >> 2;            // 0..63
    const int wlk = (tid & 3) * 4;       // 0,4,8,12
    const float* Ag = A + (size_t)(row0 + alr) * DIMC + alk;
    const float* Wg = W + (size_t)(col0 + wlr) * DIMC + wlk;

    // fragment base offsets (floats) within a buffer
    const int gr = lane >> 2;            // 0..7
    const int gc = lane & 3;             // 0..3
    const int aB = (wm * 32 + gr) * 20 + gc;   // A(m,k): +160 row+8, +320 mi=1, +4 k+4
    const int bB = (wn * 32 + gr) * 20 + gc;   // B(k,n)=W[n][k]: +160 per nj, +4 k+4

    float c000=0.f,c001=0.f,c002=0.f,c003=0.f, c010=0.f,c011=0.f,c012=0.f,c013=0.f;
    float c020=0.f,c021=0.f,c022=0.f,c023=0.f, c030=0.f,c031=0.f,c032=0.f,c033=0.f;
    float c100=0.f,c101=0.f,c102=0.f,c103=0.f, c110=0.f,c111=0.f,c112=0.f,c113=0.f;
    float c120=0.f,c121=0.f,c122=0.f,c123=0.f, c130=0.f,c131=0.f,c132=0.f,c133=0.f;

    float4 pa0 = *(const float4*)(Ag);
    float4 pa1 = *(const float4*)(Ag + 4);
    float4 pw  = *(const float4*)(Wg);

#define GSTEP(K8) {                                                                  \
    const float a00=ab[aB+(K8)],     a01=ab[aB+160+(K8)],                            \
                a02=ab[aB+4+(K8)],   a03=ab[aB+164+(K8)];                            \
    const float a10=ab[aB+320+(K8)], a11=ab[aB+480+(K8)],                            \
                a12=ab[aB+324+(K8)], a13=ab[aB+484+(K8)];                            \
    const float b00=bb[bB+(K8)],     b01=bb[bB+4+(K8)];                              \
    const float b10=bb[bB+160+(K8)], b11=bb[bB+164+(K8)];                            \
    const float b20=bb[bB+320+(K8)], b21=bb[bB+324+(K8)];                            \
    const float b30=bb[bB+480+(K8)], b31=bb[bB+484+(K8)];                            \
    MMA(c000,c001,c002,c003, a00,a01,a02,a03, b00,b01);                              \
    MMA(c010,c011,c012,c013, a00,a01,a02,a03, b10,b11);                              \
    MMA(c020,c021,c022,c023, a00,a01,a02,a03, b20,b21);                              \
    MMA(c030,c031,c032,c033, a00,a01,a02,a03, b30,b31);                              \
    MMA(c100,c101,c102,c103, a10,a11,a12,a13, b00,b01);                              \
    MMA(c110,c111,c112,c113, a10,a11,a12,a13, b10,b11);                              \
    MMA(c120,c121,c122,c123, a10,a11,a12,a13, b20,b21);                              \
    MMA(c130,c131,c132,c133, a10,a11,a12,a13, b30,b31); }

#pragma unroll 1
    for (int it = 0; it < 64; ++it) {
        const int buf = it & 1;
        float* sa = As[buf] + alr * 20 + alk;
        sa[0]=tf32r(pa0.x); sa[1]=tf32r(pa0.y); sa[2]=tf32r(pa0.z); sa[3]=tf32r(pa0.w);
        sa[4]=tf32r(pa1.x); sa[5]=tf32r(pa1.y); sa[6]=tf32r(pa1.z); sa[7]=tf32r(pa1.w);
        float* sw = Ws[buf] + wlr * 20 + wlk;
        sw[0]=tf32r(pw.x); sw[1]=tf32r(pw.y); sw[2]=tf32r(pw.z); sw[3]=tf32r(pw.w);
        __syncthreads();

        if (it + 1 < 64) {
            const int k0 = (it + 1) * 16;
            pa0 = *(const float4*)(Ag + k0);
            pa1 = *(const float4*)(Ag + k0 + 4);
            pw  = *(const float4*)(Wg + k0);
        }

        const float* ab = As[buf];
        const float* bb = Ws[buf];
        GSTEP(0)
        GSTEP(8)
        // next iteration writes the other buffer: no trailing sync needed
    }
#undef GSTEP

    // ---------------- epilogue ----------------
#define EPI(MI, NJ, C0, C1, C2, C3) {                                                \
    const int m0 = row0 + wm*32 + (MI)*16 + gr;                                      \
    const int j  = col0 + wn*32 + (NJ)*8 + 2*gc;                                     \
    const float be = bias[j], bo = bias[j + 1];                                      \
    if (MODE == 1) {                                                                 \
        *(float2*)(C + (size_t)m0 * DIMC + j)       = make_float2((C0)+be,(C1)+bo);  \
        *(float2*)(C + (size_t)(m0 + 8) * DIMC + j) = make_float2((C2)+be,(C3)+bo);  \
    } else {                                                                         \
        const int sec   = j >> 10;                                                   \
        const int local = j & 1023;                                                  \
        const int h     = local >> 6;                                                \
        const int d     = local & 63;                                                \
        const float inv = exp2f(-(float)d * (LOG2_BASE / 64.0f));                    \
        float* basep = (sec == 0) ? g_Q : ((sec == 1) ? g_K : g_V);                  \
        {   const int m = m0;  const int b = m >> 11; const int n = m & 2047;        \
            float e = (C0) + be, o = (C1) + bo; float eo, oo;                        \
            if (sec == 2) { eo = e; oo = o; }                                        \
            else { float sv, cv; sincosf((float)n * inv, &sv, &cv);                  \
                   eo = e * cv - o * sv; oo = e * sv + o * cv;                       \
                   if (sec == 0) { eo *= 0.125f; oo *= 0.125f; } }                   \
            *(float2*)(basep + ((size_t)((b*NHEAD + h)*SEQ + n))*HD + d)             \
                = make_float2(eo, oo); }                                             \
        {   const int m = m0 + 8; const int b = m >> 11; const int n = m & 2047;     \
            float e = (C2) + be, o = (C3) + bo; float eo, oo;                        \
            if (sec == 2) { eo = e; oo = o; }                                        \
            else { float sv, cv; sincosf((float)n * inv, &sv, &cv);                  \
                   eo = e * cv - o * sv; oo = e * sv + o * cv;                       \
                   if (sec == 0) { eo *= 0.125f; oo *= 0.125f; } }                   \
            *(float2*)(basep + ((size_t)((b*NHEAD + h)*SEQ + n))*HD + d)             \
                = make_float2(eo, oo); }                                             \
    } }

    EPI(0,0, c000,c001,c002,c003)  EPI(0,1, c010,c011,c012,c013)
    EPI(0,2, c020,c021,c022,c023)  EPI(0,3, c030,c031,c032,c033)
    EPI(1,0, c100,c101,c102,c103)  EPI(1,1, c110,c111,c112,c113)
    EPI(1,2, c120,c121,c122,c123)  EPI(1,3, c130,c131,c132,c133)
#undef EPI
}

// ---------------------------------------------------------------------------
// TF32 flash attention. Block = 64 q rows x one (b,h), 128 threads (4 warps,
// 16 rows each). KV tile 32. S = Q@K^T via mma; quad-shuffle online softmax;
// P C-frag -> A-frag via shuffles; O += P@V via mma. 35 KB static smem.
// Strides: Qs/Ks 68, Vs 72 — all fragment LDS patterns conflict-free.
// ---------------------------------------------------------------------------
__global__ __launch_bounds__(128)
void tattn()
{
    __shared__ float Qs[64 * 68];
    __shared__ float Ks[32 * 68];
    __shared__ float Vs[32 * 72];

    const int tid  = threadIdx.x;
    const int lane = tid & 31;
    const int w    = tid >> 5;      // 0..3
    const int bh   = blockIdx.y;
    const int q0   = blockIdx.x * 64;

    const size_t base = (size_t)bh * SEQ * HD;
    const float* Qg = g_Q + base;
    const float* Kg = g_K + base;
    const float* Vg = g_V + base;

    // stage Q (tf32-rounded)
    for (int t = tid; t < 1024; t += 128) {
        const int r = t >> 4, c = (t & 15) * 4;
        float4 v = *(const float4*)(Qg + (size_t)(q0 + r) * HD + c);
        float* d = Qs + r * 68 + c;
        d[0]=tf32r(v.x); d[1]=tf32r(v.y); d[2]=tf32r(v.z); d[3]=tf32r(v.w);
    }

    const int gr = lane >> 2;        // 0..7
    const int gc = lane & 3;         // 0..3
    const int aQ = (w * 16 + gr) * 68 + gc;   // +544 row+8, +4 col+4, +K8
    const int bK = gr * 68 + gc;              // +544 per nj, +4 k+4, +K8
    const int bV = gc * 72 + gr;              // +576 per t, +288 k+4, +8 per nj
    const int s0l = (lane & ~3) | (gc >> 1);
    const int s1l = s0l + 2;
    const bool odd = (gc & 1) != 0;

    float o00=0.f,o01=0.f,o02=0.f,o03=0.f, o10=0.f,o11=0.f,o12=0.f,o13=0.f;
    float o20=0.f,o21=0.f,o22=0.f,o23=0.f, o30=0.f,o31=0.f,o32=0.f,o33=0.f;
    float o40=0.f,o41=0.f,o42=0.f,o43=0.f, o50=0.f,o51=0.f,o52=0.f,o53=0.f;
    float o60=0.f,o61=0.f,o62=0.f,o63=0.f, o70=0.f,o71=0.f,o72=0.f,o73=0.f;
    float m0 = -CUDART_INF_F, m1 = -CUDART_INF_F, l0 = 0.f, l1 = 0.f;

#define SSTEP(K8) {                                                                  \
    const float a0=Qs[aQ+(K8)], a1=Qs[aQ+544+(K8)],                                  \
                a2=Qs[aQ+4+(K8)], a3=Qs[aQ+548+(K8)];                                \
    MMA(s00,s01,s02,s03, a0,a1,a2,a3, Ks[bK+(K8)],      Ks[bK+4+(K8)]);              \
    MMA(s10,s11,s12,s13, a0,a1,a2,a3, Ks[bK+544+(K8)],  Ks[bK+548+(K8)]);            \
    MMA(s20,s21,s22,s23, a0,a1,a2,a3, Ks[bK+1088+(K8)], Ks[bK+1092+(K8)]);           \
    MMA(s30,s31,s32,s33, a0,a1,a2,a3, Ks[bK+1632+(K8)], Ks[bK+1636+(K8)]); }

#define PSTEP(T) {                                                                   \
    const float u0 = __shfl_sync(0xffffffffu, s##T##0, s0l);                         \
    const float u1 = __shfl_sync(0xffffffffu, s##T##1, s0l);                         \
    const float u2 = __shfl_sync(0xffffffffu, s##T##2, s0l);                         \
    const float u3 = __shfl_sync(0xffffffffu, s##T##3, s0l);                         \
    const float x0 = __shfl_sync(0xffffffffu, s##T##0, s1l);                         \
    const float x1 = __shfl_sync(0xffffffffu, s##T##1, s1l);                         \
    const float x2 = __shfl_sync(0xffffffffu, s##T##2, s1l);                         \
    const float x3 = __shfl_sync(0xffffffffu, s##T##3, s1l);                         \
    const float pa0 = odd ? u1 : u0;                                                 \
    const float pa1 = odd ? u3 : u2;                                                 \
    const float pa2 = odd ? x1 : x0;                                                 \
    const float pa3 = odd ? x3 : x2;                                                 \
    const int vb = bV + (T) * 576;                                                   \
    MMA(o00,o01,o02,o03, pa0,pa1,pa2,pa3, Vs[vb],    Vs[vb+288]);                    \
    MMA(o10,o11,o12,o13, pa0,pa1,pa2,pa3, Vs[vb+8],  Vs[vb+296]);                    \
    MMA(o20,o21,o22,o23, pa0,pa1,pa2,pa3, Vs[vb+16], Vs[vb+304]);                    \
    MMA(o30,o31,o32,o33, pa0,pa1,pa2,pa3, Vs[vb+24], Vs[vb+312]);                    \
    MMA(o40,o41,o42,o43, pa0,pa1,pa2,pa3, Vs[vb+32], Vs[vb+320]);                    \
    MMA(o50,o51,o52,o53, pa0,pa1,pa2,pa3, Vs[vb+40], Vs[vb+328]);                    \
    MMA(o60,o61,o62,o63, pa0,pa1,pa2,pa3, Vs[vb+48], Vs[vb+336]);                    \
    MMA(o70,o71,o72,o73, pa0,pa1,pa2,pa3, Vs[vb+56], Vs[vb+344]); }

#pragma unroll 1
    for (int kt = 0; kt < 64; ++kt) {
        const int k0 = kt * 32;
        __syncthreads();   // protect Ks/Vs from previous iteration (and Qs stage on kt=0)
        for (int t = tid; t < 512; t += 128) {
            const int r = t >> 4, c = (t & 15) * 4;
            float4 kv = *(const float4*)(Kg + (size_t)(k0 + r) * HD + c);
            float4 vv = *(const float4*)(Vg + (size_t)(k0 + r) * HD + c);
            float* dk = Ks + r * 68 + c;
            float* dv = Vs + r * 72 + c;
            dk[0]=tf32r(kv.x); dk[1]=tf32r(kv.y); dk[2]=tf32r(kv.z); dk[3]=tf32r(kv.w);
            dv[0]=tf32r(vv.x); dv[1]=tf32r(vv.y); dv[2]=tf32r(vv.z); dv[3]=tf32r(vv.w);
        }
        __syncthreads();

        // ---- S = Q @ K^T ----
        float s00=0.f,s01=0.f,s02=0.f,s03=0.f, s10=0.f,s11=0.f,s12=0.f,s13=0.f;
        float s20=0.f,s21=0.f,s22=0.f,s23=0.f, s30=0.f,s31=0.f,s32=0.f,s33=0.f;
        SSTEP(0)  SSTEP(8)  SSTEP(16) SSTEP(24)
        SSTEP(32) SSTEP(40) SSTEP(48) SSTEP(56)

        // ---- online softmax (row gr via quad shfl 1,2) ----
        {
            float mx0 = fmaxf(fmaxf(fmaxf(s00,s01), fmaxf(s10,s11)),
                              fmaxf(fmaxf(s20,s21), fmaxf(s30,s31)));
            float mx1 = fmaxf(fmaxf(fmaxf(s02,s03), fmaxf(s12,s13)),
                              fmaxf(fmaxf(s22,s23), fmaxf(s32,s33)));
            mx0 = fmaxf(mx0, __shfl_xor_sync(0xffffffffu, mx0, 1));
            mx0 = fmaxf(mx0, __shfl_xor_sync(0xffffffffu, mx0, 2));
            mx1 = fmaxf(mx1, __shfl_xor_sync(0xffffffffu, mx1, 1));
            mx1 = fmaxf(mx1, __shfl_xor_sync(0xffffffffu, mx1, 2));
            const float mn0 = fmaxf(m0, mx0);
            const float mn1 = fmaxf(m1, mx1);
            const float al0 = __expf(m0 - mn0);
            const float al1 = __expf(m1 - mn1);
            s00=tf32r(__expf(s00-mn0)); s01=tf32r(__expf(s01-mn0));
            s10=tf32r(__expf(s10-mn0)); s11=tf32r(__expf(s11-mn0));
            s20=tf32r(__expf(s20-mn0)); s21=tf32r(__expf(s21-mn0));
            s30=tf32r(__expf(s30-mn0)); s31=tf32r(__expf(s31-mn0));
            s02=tf32r(__expf(s02-mn1)); s03=tf32r(__expf(s03-mn1));
            s12=tf32r(__expf(s12-mn1)); s13=tf32r(__expf(s13-mn1));
            s22=tf32r(__expf(s22-mn1)); s23=tf32r(__expf(s23-mn1));
            s32=tf32r(__expf(s32-mn1)); s33=tf32r(__expf(s33-mn1));
            float sum0 = ((s00+s01)+(s10+s11)) + ((s20+s21)+(s30+s31));
            float sum1 = ((s02+s03)+(s12+s13)) + ((s22+s23)+(s32+s33));
            sum0 += __shfl_xor_sync(0xffffffffu, sum0, 1);
            sum0 += __shfl_xor_sync(0xffffffffu, sum0, 2);
            sum1 += __shfl_xor_sync(0xffffffffu, sum1, 1);
            sum1 += __shfl_xor_sync(0xffffffffu, sum1, 2);
            l0 = l0 * al0 + sum0;  m0 = mn0;
            l1 = l1 * al1 + sum1;  m1 = mn1;
            o00*=al0; o01*=al0; o10*=al0; o11*=al0; o20*=al0; o21*=al0; o30*=al0; o31*=al0;
            o40*=al0; o41*=al0; o50*=al0; o51*=al0; o60*=al0; o61*=al0; o70*=al0; o71*=al0;
            o02*=al1; o03*=al1; o12*=al1; o13*=al1; o22*=al1; o23*=al1; o32*=al1; o33*=al1;
            o42*=al1; o43*=al1; o52*=al1; o53*=al1; o62*=al1; o63*=al1; o72*=al1; o73*=al1;
        }

        // ---- O += P @ V ----
        PSTEP(0) PSTEP(1) PSTEP(2) PSTEP(3)
    }
#undef SSTEP
#undef PSTEP

    // ---- normalize + write O to g_O [B,N,1024] ----
    {
        const float il0 = 1.f / l0;
        const float il1 = 1.f / l1;
        const int b = bh >> 4;
        const int h = bh & 15;
        const int n = q0 + w * 16 + gr;
        float* O0 = g_O + ((size_t)(b * SEQ + n)) * DIMC + h * HD + 2 * gc;
        float* O1 = O0 + (size_t)8 * DIMC;
        *(float2*)(O0 + 0)  = make_float2(o00*il0, o01*il0);
        *(float2*)(O0 + 8)  = make_float2(o10*il0, o11*il0);
        *(float2*)(O0 + 16) = make_float2(o20*il0, o21*il0);
        *(float2*)(O0 + 24) = make_float2(o30*il0, o31*il0);
        *(float2*)(O0 + 32) = make_float2(o40*il0, o41*il0);
        *(float2*)(O0 + 40) = make_float2(o50*il0, o51*il0);
        *(float2*)(O0 + 48) = make_float2(o60*il0, o61*il0);
        *(float2*)(O0 + 56) = make_float2(o70*il0, o71*il0);
        *(float2*)(O1 + 0)  = make_float2(o02*il1, o03*il1);
        *(float2*)(O1 + 8)  = make_float2(o12*il1, o13*il1);
        *(float2*)(O1 + 16) = make_float2(o22*il1, o23*il1);
        *(float2*)(O1 + 24) = make_float2(o32*il1, o33*il1);
        *(float2*)(O1 + 32) = make_float2(o42*il1, o43*il1);
        *(float2*)(O1 + 40) = make_float2(o52*il1, o53*il1);
        *(float2*)(O1 + 48) = make_float2(o62*il1, o63*il1);
        *(float2*)(O1 + 56) = make_float2(o72*il1, o73*il1);
    }
}

// ---------------------------------------------------------------------------

extern "C" void kernel_launch(void* const* d_in, const int* in_sizes, int n_in,
                              void* d_out, int out_size)
{
    const float* x      = (const float*)d_in[0];
    const float* qkv_w  = (const float*)d_in[1];
    const float* qkv_b  = (const float*)d_in[2];
    const float* proj_w = (const float*)d_in[3];
    const float* proj_b = (const float*)d_in[4];
    float* out = (float*)d_out;

    tgemm<0><<<dim3(QKVN / 64, MTOT / 128), 256>>>(x, qkv_w, qkv_b, nullptr);
    tattn<<<dim3(SEQ / 64, BATCH * NHEAD), 128>>>();
    tgemm<1><<<dim3(DIMC / 64, MTOT / 128), 256>>>(nullptr, proj_w, proj_b, out);
}

// round 10
// speedup vs baseline: 2.5262x; 1.0187x over previous
// TF32 mma.sync pipeline v2b — R9 with the attention smem geometry corrected
// (K/V tiles are 32 kv x 64 d -> strides 68/72, the R8-proven values).
// GEMM warp tile 64x32; attention Q register-resident. Array-free scalars.
#include <cuda_runtime.h>
#include <math_constants.h>

#define DIMC   1024
#define NHEAD  16
#define HD     64
#define BATCH  2
#define SEQ    2048
#define MTOT   (BATCH*SEQ)          // 4096
#define QKVN   (3*DIMC)             // 3072
#define LOG2_BASE 13.287712379549449f

// ---- device-global scratch: exactly the proven 64 MiB ----
__device__ float g_Q[BATCH*NHEAD*SEQ*HD];     // [bh][n][d]
__device__ float g_K[BATCH*NHEAD*SEQ*HD];     // [bh][n][d]
__device__ float g_V[BATCH*NHEAD*SEQ*HD];     // [bh][n][d]
__device__ float g_O[MTOT*DIMC];              // [m][1024]

// RNE round-to-tf32 in pure integer math (no asm)
__device__ __forceinline__ float tf32r(float x) {
    unsigned u = __float_as_uint(x);
    u = (u + 0x0FFFu + ((u >> 13) & 1u)) & 0xFFFFE000u;
    return __uint_as_float(u);
}

// m16n8k8 tf32 mma: D += A*B. All operands individual scalars.
#define MMA(d0,d1,d2,d3, a0,a1,a2,a3, b0,b1)                                   \
    asm volatile("mma.sync.aligned.m16n8k8.row.col.f32.tf32.tf32.f32 "         \
                 "{%0,%1,%2,%3},{%4,%5,%6,%7},{%8,%9},{%0,%1,%2,%3};"          \
                 : "+f"(d0), "+f"(d1), "+f"(d2), "+f"(d3)                      \
                 : "r"(__float_as_uint(a0)), "r"(__float_as_uint(a1)),         \
                   "r"(__float_as_uint(a2)), "r"(__float_as_uint(a3)),         \
                   "r"(__float_as_uint(b0)), "r"(__float_as_uint(b1)))

// ---------------------------------------------------------------------------
// TF32 GEMM: C[M,N] = A[M,1024] @ W[N,1024]^T (+bias; +RoPE for MODE 0)
// BM=BN=128, BK=16. 8 warps as 2(m) x 4(n); warp tile 64x32 (4 mi x 4 nj
// fragments, 64 named acc scalars). smem stride 20 (proven conflict-free).
// One __syncthreads per k-tile (ping-pong + register prefetch).
// ---------------------------------------------------------------------------
template<int MODE>   // 0 = QKV (+bias+RoPE, scatter to g_Q/g_K/g_V), 1 = proj
__global__ __launch_bounds__(256)
void tgemm(const float* __restrict__ A_in, const float* __restrict__ W,
           const float* __restrict__ bias, float* __restrict__ C)
{
    __shared__ float As[2][128 * 20];
    __shared__ float Ws[2][128 * 20];

    const int tid  = threadIdx.x;
    const int lane = tid & 31;
    const int w    = tid >> 5;
    const int wm   = w >> 2;         // 0..1 (M, 64 rows each)
    const int wn   = w & 3;          // 0..3 (N, 32 cols each)
    const int row0 = blockIdx.y * 128;
    const int col0 = blockIdx.x * 128;

    const float* A = (MODE == 0) ? A_in : g_O;

    // loaders: thread owns one row of A and one row of W, 8 of 16 k's
    const int lr = tid >> 1;             // 0..127
    const int lk = (tid & 1) * 8;        // 0 or 8
    const float* Ag = A + (size_t)(row0 + lr) * DIMC + lk;
    const float* Wg = W + (size_t)(col0 + lr) * DIMC + lk;

    const int gr = lane >> 2;            // 0..7
    const int gc = lane & 3;             // 0..3
    const int aA = (wm * 64 + gr) * 20 + gc;   // +320 per mi, +160 row+8, +4 col+4
    const int bW = (wn * 32 + gr) * 20 + gc;   // +160 per nj, +4 k+4

    // 64 named accumulators: c<mi><nj>_<e>
    float c00_0=0.f,c00_1=0.f,c00_2=0.f,c00_3=0.f, c01_0=0.f,c01_1=0.f,c01_2=0.f,c01_3=0.f;
    float c02_0=0.f,c02_1=0.f,c02_2=0.f,c02_3=0.f, c03_0=0.f,c03_1=0.f,c03_2=0.f,c03_3=0.f;
    float c10_0=0.f,c10_1=0.f,c10_2=0.f,c10_3=0.f, c11_0=0.f,c11_1=0.f,c11_2=0.f,c11_3=0.f;
    float c12_0=0.f,c12_1=0.f,c12_2=0.f,c12_3=0.f, c13_0=0.f,c13_1=0.f,c13_2=0.f,c13_3=0.f;
    float c20_0=0.f,c20_1=0.f,c20_2=0.f,c20_3=0.f, c21_0=0.f,c21_1=0.f,c21_2=0.f,c21_3=0.f;
    float c22_0=0.f,c22_1=0.f,c22_2=0.f,c22_3=0.f, c23_0=0.f,c23_1=0.f,c23_2=0.f,c23_3=0.f;
    float c30_0=0.f,c30_1=0.f,c30_2=0.f,c30_3=0.f, c31_0=0.f,c31_1=0.f,c31_2=0.f,c31_3=0.f;
    float c32_0=0.f,c32_1=0.f,c32_2=0.f,c32_3=0.f, c33_0=0.f,c33_1=0.f,c33_2=0.f,c33_3=0.f;

    float4 pa0 = *(const float4*)(Ag);
    float4 pa1 = *(const float4*)(Ag + 4);
    float4 pw0 = *(const float4*)(Wg);
    float4 pw1 = *(const float4*)(Wg + 4);

#define GSTEP(K8) {                                                                  \
    const float a0_0=ab[aA+(K8)],     a0_1=ab[aA+160+(K8)],                          \
                a0_2=ab[aA+4+(K8)],   a0_3=ab[aA+164+(K8)];                          \
    const float a1_0=ab[aA+320+(K8)], a1_1=ab[aA+480+(K8)],                          \
                a1_2=ab[aA+324+(K8)], a1_3=ab[aA+484+(K8)];                          \
    const float a2_0=ab[aA+640+(K8)], a2_1=ab[aA+800+(K8)],                          \
                a2_2=ab[aA+644+(K8)], a2_3=ab[aA+804+(K8)];                          \
    const float a3_0=ab[aA+960+(K8)], a3_1=ab[aA+1120+(K8)],                         \
                a3_2=ab[aA+964+(K8)], a3_3=ab[aA+1124+(K8)];                         \
    const float b0_0=bb[bW+(K8)],     b0_1=bb[bW+4+(K8)];                            \
    const float b1_0=bb[bW+160+(K8)], b1_1=bb[bW+164+(K8)];                          \
    const float b2_0=bb[bW+320+(K8)], b2_1=bb[bW+324+(K8)];                          \
    const float b3_0=bb[bW+480+(K8)], b3_1=bb[bW+484+(K8)];                          \
    MMA(c00_0,c00_1,c00_2,c00_3, a0_0,a0_1,a0_2,a0_3, b0_0,b0_1);                    \
    MMA(c01_0,c01_1,c01_2,c01_3, a0_0,a0_1,a0_2,a0_3, b1_0,b1_1);                    \
    MMA(c02_0,c02_1,c02_2,c02_3, a0_0,a0_1,a0_2,a0_3, b2_0,b2_1);                    \
    MMA(c03_0,c03_1,c03_2,c03_3, a0_0,a0_1,a0_2,a0_3, b3_0,b3_1);                    \
    MMA(c10_0,c10_1,c10_2,c10_3, a1_0,a1_1,a1_2,a1_3, b0_0,b0_1);                    \
    MMA(c11_0,c11_1,c11_2,c11_3, a1_0,a1_1,a1_2,a1_3, b1_0,b1_1);                    \
    MMA(c12_0,c12_1,c12_2,c12_3, a1_0,a1_1,a1_2,a1_3, b2_0,b2_1);                    \
    MMA(c13_0,c13_1,c13_2,c13_3, a1_0,a1_1,a1_2,a1_3, b3_0,b3_1);                    \
    MMA(c20_0,c20_1,c20_2,c20_3, a2_0,a2_1,a2_2,a2_3, b0_0,b0_1);                    \
    MMA(c21_0,c21_1,c21_2,c21_3, a2_0,a2_1,a2_2,a2_3, b1_0,b1_1);                    \
    MMA(c22_0,c22_1,c22_2,c22_3, a2_0,a2_1,a2_2,a2_3, b2_0,b2_1);                    \
    MMA(c23_0,c23_1,c23_2,c23_3, a2_0,a2_1,a2_2,a2_3, b3_0,b3_1);                    \
    MMA(c30_0,c30_1,c30_2,c30_3, a3_0,a3_1,a3_2,a3_3, b0_0,b0_1);                    \
    MMA(c31_0,c31_1,c31_2,c31_3, a3_0,a3_1,a3_2,a3_3, b1_0,b1_1);                    \
    MMA(c32_0,c32_1,c32_2,c32_3, a3_0,a3_1,a3_2,a3_3, b2_0,b2_1);                    \
    MMA(c33_0,c33_1,c33_2,c33_3, a3_0,a3_1,a3_2,a3_3, b3_0,b3_1); }

#pragma unroll 1
    for (int it = 0; it < 64; ++it) {
        const int buf = it & 1;
        float* sa = As[buf] + lr * 20 + lk;
        sa[0]=tf32r(pa0.x); sa[1]=tf32r(pa0.y); sa[2]=tf32r(pa0.z); sa[3]=tf32r(pa0.w);
        sa[4]=tf32r(pa1.x); sa[5]=tf32r(pa1.y); sa[6]=tf32r(pa1.z); sa[7]=tf32r(pa1.w);
        float* sw = Ws[buf] + lr * 20 + lk;
        sw[0]=tf32r(pw0.x); sw[1]=tf32r(pw0.y); sw[2]=tf32r(pw0.z); sw[3]=tf32r(pw0.w);
        sw[4]=tf32r(pw1.x); sw[5]=tf32r(pw1.y); sw[6]=tf32r(pw1.z); sw[7]=tf32r(pw1.w);
        __syncthreads();

        if (it + 1 < 64) {
            const int k0 = (it + 1) * 16;
            pa0 = *(const float4*)(Ag + k0);
            pa1 = *(const float4*)(Ag + k0 + 4);
            pw0 = *(const float4*)(Wg + k0);
            pw1 = *(const float4*)(Wg + k0 + 4);
        }

        const float* ab = As[buf];
        const float* bb = Ws[buf];
        GSTEP(0)
        GSTEP(8)
        // next iteration writes the other buffer: no trailing sync needed
    }
#undef GSTEP

    // ---------------- epilogue ----------------
#define EPI(MI, NJ, C0, C1, C2, C3) {                                                \
    const int m0 = row0 + wm*64 + (MI)*16 + gr;                                      \
    const int j  = col0 + wn*32 + (NJ)*8 + 2*gc;                                     \
    const float be = bias[j], bo = bias[j + 1];                                      \
    if (MODE == 1) {                                                                 \
        *(float2*)(C + (size_t)m0 * DIMC + j)       = make_float2((C0)+be,(C1)+bo);  \
        *(float2*)(C + (size_t)(m0 + 8) * DIMC + j) = make_float2((C2)+be,(C3)+bo);  \
    } else {                                                                         \
        const int sec   = j >> 10;                                                   \
        const int local = j & 1023;                                                  \
        const int h     = local >> 6;                                                \
        const int d     = local & 63;                                                \
        const float inv = exp2f(-(float)d * (LOG2_BASE / 64.0f));                    \
        float* basep = (sec == 0) ? g_Q : ((sec == 1) ? g_K : g_V);                  \
        {   const int m = m0;  const int b = m >> 11; const int n = m & 2047;        \
            float e = (C0) + be, o = (C1) + bo; float eo, oo;                        \
            if (sec == 2) { eo = e; oo = o; }                                        \
            else { float sv, cv; sincosf((float)n * inv, &sv, &cv);                  \
                   eo = e * cv - o * sv; oo = e * sv + o * cv;                       \
                   if (sec == 0) { eo *= 0.125f; oo *= 0.125f; } }                   \
            *(float2*)(basep + ((size_t)((b*NHEAD + h)*SEQ + n))*HD + d)             \
                = make_float2(eo, oo); }                                             \
        {   const int m = m0 + 8; const int b = m >> 11; const int n = m & 2047;     \
            float e = (C2) + be, o = (C3) + bo; float eo, oo;                        \
            if (sec == 2) { eo = e; oo = o; }                                        \
            else { float sv, cv; sincosf((float)n * inv, &sv, &cv);                  \
                   eo = e * cv - o * sv; oo = e * sv + o * cv;                       \
                   if (sec == 0) { eo *= 0.125f; oo *= 0.125f; } }                   \
            *(float2*)(basep + ((size_t)((b*NHEAD + h)*SEQ + n))*HD + d)             \
                = make_float2(eo, oo); }                                             \
    } }

    EPI(0,0, c00_0,c00_1,c00_2,c00_3)  EPI(0,1, c01_0,c01_1,c01_2,c01_3)
    EPI(0,2, c02_0,c02_1,c02_2,c02_3)  EPI(0,3, c03_0,c03_1,c03_2,c03_3)
    EPI(1,0, c10_0,c10_1,c10_2,c10_3)  EPI(1,1, c11_0,c11_1,c11_2,c11_3)
    EPI(1,2, c12_0,c12_1,c12_2,c12_3)  EPI(1,3, c13_0,c13_1,c13_2,c13_3)
    EPI(2,0, c20_0,c20_1,c20_2,c20_3)  EPI(2,1, c21_0,c21_1,c21_2,c21_3)
    EPI(2,2, c22_0,c22_1,c22_2,c22_3)  EPI(2,3, c23_0,c23_1,c23_2,c23_3)
    EPI(3,0, c30_0,c30_1,c30_2,c30_3)  EPI(3,1, c31_0,c31_1,c31_2,c31_3)
    EPI(3,2, c32_0,c32_1,c32_2,c32_3)  EPI(3,3, c33_0,c33_1,c33_2,c33_3)
#undef EPI
}

// ---------------------------------------------------------------------------
// TF32 flash attention. Block = 64 q rows x one (b,h), 128 threads (4 warps,
// 16 q-rows each). KV tile 32. Q register-resident (32 scalars/thread).
// smem: Ks[32][68] + Vs[32][72] = 17.9 KB (R8-proven strides / offsets).
// S via mma; quad-shuffle online softmax; P C->A frag via shuffles; PV mma.
// ---------------------------------------------------------------------------
__global__ __launch_bounds__(128)
void tattn()
{
    __shared__ float Ks[32 * 68];
    __shared__ float Vs[32 * 72];

    const int tid  = threadIdx.x;
    const int lane = tid & 31;
    const int w    = tid >> 5;      // 0..3
    const int bh   = blockIdx.y;
    const int q0   = blockIdx.x * 64;

    const size_t base = (size_t)bh * SEQ * HD;
    const float* Qg = g_Q + base;
    const float* Kg = g_K + base;
    const float* Vg = g_V + base;

    const int gr = lane >> 2;        // 0..7
    const int gc = lane & 3;         // 0..3

    // ---- Q A-fragments, register resident (32 scalars) ----
    const float* Qb = Qg + (size_t)(q0 + w * 16 + gr) * HD + gc;
#define QLD(K8) \
    const float qa##K8##_0 = tf32r(Qb[(K8)*8]);        \
    const float qa##K8##_1 = tf32r(Qb[512 + (K8)*8]);  \
    const float qa##K8##_2 = tf32r(Qb[(K8)*8 + 4]);    \
    const float qa##K8##_3 = tf32r(Qb[512 + (K8)*8 + 4]);
    QLD(0) QLD(1) QLD(2) QLD(3) QLD(4) QLD(5) QLD(6) QLD(7)
#undef QLD

    const int kB = gr * 68 + gc;     // K frag: + nj*544 + k8*8; b1 = +4
    const int vB = gc * 72 + gr;     // V frag: + T*576 + nj*8;  b1 = +288
    const int s0l = (lane & ~3) | (gc >> 1);
    const int s1l = s0l + 2;
    const bool odd = (gc & 1) != 0;

    float o00=0.f,o01=0.f,o02=0.f,o03=0.f, o10=0.f,o11=0.f,o12=0.f,o13=0.f;
    float o20=0.f,o21=0.f,o22=0.f,o23=0.f, o30=0.f,o31=0.f,o32=0.f,o33=0.f;
    float o40=0.f,o41=0.f,o42=0.f,o43=0.f, o50=0.f,o51=0.f,o52=0.f,o53=0.f;
    float o60=0.f,o61=0.f,o62=0.f,o63=0.f, o70=0.f,o71=0.f,o72=0.f,o73=0.f;
    float m0 = -CUDART_INF_F, m1 = -CUDART_INF_F, l0 = 0.f, l1 = 0.f;

#define SSTEP(K8) {                                                                  \
    MMA(s00,s01,s02,s03, qa##K8##_0,qa##K8##_1,qa##K8##_2,qa##K8##_3,                \
        Ks[kB+(K8)*8],      Ks[kB+4+(K8)*8]);                                        \
    MMA(s10,s11,s12,s13, qa##K8##_0,qa##K8##_1,qa##K8##_2,qa##K8##_3,                \
        Ks[kB+544+(K8)*8],  Ks[kB+548+(K8)*8]);                                      \
    MMA(s20,s21,s22,s23, qa##K8##_0,qa##K8##_1,qa##K8##_2,qa##K8##_3,                \
        Ks[kB+1088+(K8)*8], Ks[kB+1092+(K8)*8]);                                     \
    MMA(s30,s31,s32,s33, qa##K8##_0,qa##K8##_1,qa##K8##_2,qa##K8##_3,                \
        Ks[kB+1632+(K8)*8], Ks[kB+1636+(K8)*8]); }

#define PSTEP(T) {                                                                   \
    const float u0 = __shfl_sync(0xffffffffu, s##T##0, s0l);                         \
    const float u1 = __shfl_sync(0xffffffffu, s##T##1, s0l);                         \
    const float u2 = __shfl_sync(0xffffffffu, s##T##2, s0l);                         \
    const float u3 = __shfl_sync(0xffffffffu, s##T##3, s0l);                         \
    const float x0 = __shfl_sync(0xffffffffu, s##T##0, s1l);                         \
    const float x1 = __shfl_sync(0xffffffffu, s##T##1, s1l);                         \
    const float x2 = __shfl_sync(0xffffffffu, s##T##2, s1l);                         \
    const float x3 = __shfl_sync(0xffffffffu, s##T##3, s1l);                         \
    const float pa0 = odd ? u1 : u0;                                                 \
    const float pa1 = odd ? u3 : u2;                                                 \
    const float pa2 = odd ? x1 : x0;                                                 \
    const float pa3 = odd ? x3 : x2;                                                 \
    const int vb = vB + (T) * 576;                                                   \
    MMA(o00,o01,o02,o03, pa0,pa1,pa2,pa3, Vs[vb],    Vs[vb+288]);                    \
    MMA(o10,o11,o12,o13, pa0,pa1,pa2,pa3, Vs[vb+8],  Vs[vb+296]);                    \
    MMA(o20,o21,o22,o23, pa0,pa1,pa2,pa3, Vs[vb+16], Vs[vb+304]);                    \
    MMA(o30,o31,o32,o33, pa0,pa1,pa2,pa3, Vs[vb+24], Vs[vb+312]);                    \
    MMA(o40,o41,o42,o43, pa0,pa1,pa2,pa3, Vs[vb+32], Vs[vb+320]);                    \
    MMA(o50,o51,o52,o53, pa0,pa1,pa2,pa3, Vs[vb+40], Vs[vb+328]);                    \
    MMA(o60,o61,o62,o63, pa0,pa1,pa2,pa3, Vs[vb+48], Vs[vb+336]);                    \
    MMA(o70,o71,o72,o73, pa0,pa1,pa2,pa3, Vs[vb+56], Vs[vb+344]); }

#pragma unroll 1
    for (int kt = 0; kt < 64; ++kt) {
        const int k0 = kt * 32;
        __syncthreads();   // protect Ks/Vs from previous iteration
        for (int t = tid; t < 512; t += 128) {
            const int r = t >> 4, c = (t & 15) * 4;
            float4 kv = *(const float4*)(Kg + (size_t)(k0 + r) * HD + c);
            float4 vv = *(const float4*)(Vg + (size_t)(k0 + r) * HD + c);
            *(float4*)&Ks[r * 68 + c] =
                make_float4(tf32r(kv.x), tf32r(kv.y), tf32r(kv.z), tf32r(kv.w));
            *(float4*)&Vs[r * 72 + c] =
                make_float4(tf32r(vv.x), tf32r(vv.y), tf32r(vv.z), tf32r(vv.w));
        }
        __syncthreads();

        // ---- S = Q @ K^T ----
        float s00=0.f,s01=0.f,s02=0.f,s03=0.f, s10=0.f,s11=0.f,s12=0.f,s13=0.f;
        float s20=0.f,s21=0.f,s22=0.f,s23=0.f, s30=0.f,s31=0.f,s32=0.f,s33=0.f;
        SSTEP(0) SSTEP(1) SSTEP(2) SSTEP(3)
        SSTEP(4) SSTEP(5) SSTEP(6) SSTEP(7)

        // ---- online softmax (row gr via quad shfl 1,2) ----
        {
            float mx0 = fmaxf(fmaxf(fmaxf(s00,s01), fmaxf(s10,s11)),
                              fmaxf(fmaxf(s20,s21), fmaxf(s30,s31)));
            float mx1 = fmaxf(fmaxf(fmaxf(s02,s03), fmaxf(s12,s13)),
                              fmaxf(fmaxf(s22,s23), fmaxf(s32,s33)));
            mx0 = fmaxf(mx0, __shfl_xor_sync(0xffffffffu, mx0, 1));
            mx0 = fmaxf(mx0, __shfl_xor_sync(0xffffffffu, mx0, 2));
            mx1 = fmaxf(mx1, __shfl_xor_sync(0xffffffffu, mx1, 1));
            mx1 = fmaxf(mx1, __shfl_xor_sync(0xffffffffu, mx1, 2));
            const float mn0 = fmaxf(m0, mx0);
            const float mn1 = fmaxf(m1, mx1);
            const float al0 = __expf(m0 - mn0);
            const float al1 = __expf(m1 - mn1);
            s00=tf32r(__expf(s00-mn0)); s01=tf32r(__expf(s01-mn0));
            s10=tf32r(__expf(s10-mn0)); s11=tf32r(__expf(s11-mn0));
            s20=tf32r(__expf(s20-mn0)); s21=tf32r(__expf(s21-mn0));
            s30=tf32r(__expf(s30-mn0)); s31=tf32r(__expf(s31-mn0));
            s02=tf32r(__expf(s02-mn1)); s03=tf32r(__expf(s03-mn1));
            s12=tf32r(__expf(s12-mn1)); s13=tf32r(__expf(s13-mn1));
            s22=tf32r(__expf(s22-mn1)); s23=tf32r(__expf(s23-mn1));
            s32=tf32r(__expf(s32-mn1)); s33=tf32r(__expf(s33-mn1));
            float sum0 = ((s00+s01)+(s10+s11)) + ((s20+s21)+(s30+s31));
            float sum1 = ((s02+s03)+(s12+s13)) + ((s22+s23)+(s32+s33));
            sum0 += __shfl_xor_sync(0xffffffffu, sum0, 1);
            sum0 += __shfl_xor_sync(0xffffffffu, sum0, 2);
            sum1 += __shfl_xor_sync(0xffffffffu, sum1, 1);
            sum1 += __shfl_xor_sync(0xffffffffu, sum1, 2);
            l0 = l0 * al0 + sum0;  m0 = mn0;
            l1 = l1 * al1 + sum1;  m1 = mn1;
            o00*=al0; o01*=al0; o10*=al0; o11*=al0; o20*=al0; o21*=al0; o30*=al0; o31*=al0;
            o40*=al0; o41*=al0; o50*=al0; o51*=al0; o60*=al0; o61*=al0; o70*=al0; o71*=al0;
            o02*=al1; o03*=al1; o12*=al1; o13*=al1; o22*=al1; o23*=al1; o32*=al1; o33*=al1;
            o42*=al1; o43*=al1; o52*=al1; o53*=al1; o62*=al1; o63*=al1; o72*=al1; o73*=al1;
        }

        // ---- O += P @ V ----
        PSTEP(0) PSTEP(1) PSTEP(2) PSTEP(3)
    }
#undef SSTEP
#undef PSTEP

    // ---- normalize + write O to g_O [B,N,1024] ----
    {
        const float il0 = 1.f / l0;
        const float il1 = 1.f / l1;
        const int b = bh >> 4;
        const int h = bh & 15;
        const int n = q0 + w * 16 + gr;
        float* O0 = g_O + ((size_t)(b * SEQ + n)) * DIMC + h * HD + 2 * gc;
        float* O1 = O0 + (size_t)8 * DIMC;
        *(float2*)(O0 + 0)  = make_float2(o00*il0, o01*il0);
        *(float2*)(O0 + 8)  = make_float2(o10*il0, o11*il0);
        *(float2*)(O0 + 16) = make_float2(o20*il0, o21*il0);
        *(float2*)(O0 + 24) = make_float2(o30*il0, o31*il0);
        *(float2*)(O0 + 32) = make_float2(o40*il0, o41*il0);
        *(float2*)(O0 + 40) = make_float2(o50*il0, o51*il0);
        *(float2*)(O0 + 48) = make_float2(o60*il0, o61*il0);
        *(float2*)(O0 + 56) = make_float2(o70*il0, o71*il0);
        *(float2*)(O1 + 0)  = make_float2(o02*il1, o03*il1);
        *(float2*)(O1 + 8)  = make_float2(o12*il1, o13*il1);
        *(float2*)(O1 + 16) = make_float2(o22*il1, o23*il1);
        *(float2*)(O1 + 24) = make_float2(o32*il1, o33*il1);
        *(float2*)(O1 + 32) = make_float2(o42*il1, o43*il1);
        *(float2*)(O1 + 40) = make_float2(o52*il1, o53*il1);
        *(float2*)(O1 + 48) = make_float2(o62*il1, o63*il1);
        *(float2*)(O1 + 56) = make_float2(o72*il1, o73*il1);
    }
}

// ---------------------------------------------------------------------------

extern "C" void kernel_launch(void* const* d_in, const int* in_sizes, int n_in,
                              void* d_out, int out_size)
{
    const float* x      = (const float*)d_in[0];
    const float* qkv_w  = (const float*)d_in[1];
    const float* qkv_b  = (const float*)d_in[2];
    const float* proj_w = (const float*)d_in[3];
    const float* proj_b = (const float*)d_in[4];
    float* out = (float*)d_out;

    tgemm<0><<<dim3(QKVN / 128, MTOT / 128), 256>>>(x, qkv_w, qkv_b, nullptr);
    tattn<<<dim3(SEQ / 64, BATCH * NHEAD), 128>>>();
    tgemm<1><<<dim3(DIMC / 128, MTOT / 128), 256>>>(nullptr, proj_w, proj_b, out);
}

// round 11
// speedup vs baseline: 2.9105x; 1.1521x over previous
// TF32 mma.sync pipeline v3 — permuted k-pair smem packing (LDS.64 fragment
// loads, conflict-free strides), attention q-tile 128 (halved K/V L2 traffic).
// Array-free named scalars throughout (zero stack frame, guard-safe).
#include <cuda_runtime.h>
#include <math_constants.h>

#define DIMC   1024
#define NHEAD  16
#define HD     64
#define BATCH  2
#define SEQ    2048
#define MTOT   (BATCH*SEQ)          // 4096
#define QKVN   (3*DIMC)             // 3072
#define LOG2_BASE 13.287712379549449f

// ---- device-global scratch: exactly the proven 64 MiB ----
__device__ float g_Q[BATCH*NHEAD*SEQ*HD];     // [bh][n][d]
__device__ float g_K[BATCH*NHEAD*SEQ*HD];     // [bh][n][d]
__device__ float g_V[BATCH*NHEAD*SEQ*HD];     // [bh][n][d]
__device__ float g_O[MTOT*DIMC];              // [m][1024]

// RNE round-to-tf32 in pure integer math (no asm)
__device__ __forceinline__ float tf32r(float x) {
    unsigned u = __float_as_uint(x);
    u = (u + 0x0FFFu + ((u >> 13) & 1u)) & 0xFFFFE000u;
    return __uint_as_float(u);
}

// m16n8k8 tf32 mma: D += A*B. All operands individual scalars.
#define MMA(d0,d1,d2,d3, a0,a1,a2,a3, b0,b1)                                   \
    asm volatile("mma.sync.aligned.m16n8k8.row.col.f32.tf32.tf32.f32 "         \
                 "{%0,%1,%2,%3},{%4,%5,%6,%7},{%8,%9},{%0,%1,%2,%3};"          \
                 : "+f"(d0), "+f"(d1), "+f"(d2), "+f"(d3)                      \
                 : "r"(__float_as_uint(a0)), "r"(__float_as_uint(a1)),         \
                   "r"(__float_as_uint(a2)), "r"(__float_as_uint(a3)),         \
                   "r"(__float_as_uint(b0)), "r"(__float_as_uint(b1)))

// ---------------------------------------------------------------------------
// TF32 GEMM: C[M,N] = A[M,1024] @ W[N,1024]^T (+bias; +RoPE for MODE 0)
// BM=BN=128, BK=16. 8 warps as 2(m) x 4(n); warp tile 64x32.
// smem rows hold k in PERMUTED PAIRS: within each 8-k group, (k, k+4) are
// adjacent -> every fragment k-pair is one LDS.64. Stride 24 floats:
// fragment LDS.64 addr mod 32 = gr*24 + 2gc (+const): conflict-free.
// One __syncthreads per k-tile (ping-pong + register prefetch).
// ---------------------------------------------------------------------------
template<int MODE>   // 0 = QKV (+bias+RoPE, scatter to g_Q/g_K/g_V), 1 = proj
__global__ __launch_bounds__(256)
void tgemm(const float* __restrict__ A_in, const float* __restrict__ W,
           const float* __restrict__ bias, float* __restrict__ C)
{
    __shared__ float As[2][128 * 24];
    __shared__ float Ws[2][128 * 24];

    const int tid  = threadIdx.x;
    const int lane = tid & 31;
    const int w    = tid >> 5;
    const int wm   = w >> 2;         // 0..1 (M, 64 rows each)
    const int wn   = w & 3;          // 0..3 (N, 32 cols each)
    const int row0 = blockIdx.y * 128;
    const int col0 = blockIdx.x * 128;

    const float* A = (MODE == 0) ? A_in : g_O;

    // loaders: thread owns one row of A and one row of W, one 8-k group
    const int lr = tid >> 1;             // 0..127
    const int lk = (tid & 1) * 8;        // 0 or 8 (k-group base, also smem base)
    const float* Ag = A + (size_t)(row0 + lr) * DIMC + lk;
    const float* Wg = W + (size_t)(col0 + lr) * DIMC + lk;

    const int gr = lane >> 2;            // 0..7
    const int gc = lane & 3;             // 0..3
    // fragment bases (k-pair at permuted position 2*gc within group)
    const int aA = (wm * 64 + gr) * 24 + 2 * gc;   // +384/mi, +192 row+8, +K8
    const int bW = (wn * 32 + gr) * 24 + 2 * gc;   // +192/nj, +K8

    float c00_0=0.f,c00_1=0.f,c00_2=0.f,c00_3=0.f, c01_0=0.f,c01_1=0.f,c01_2=0.f,c01_3=0.f;
    float c02_0=0.f,c02_1=0.f,c02_2=0.f,c02_3=0.f, c03_0=0.f,c03_1=0.f,c03_2=0.f,c03_3=0.f;
    float c10_0=0.f,c10_1=0.f,c10_2=0.f,c10_3=0.f, c11_0=0.f,c11_1=0.f,c11_2=0.f,c11_3=0.f;
    float c12_0=0.f,c12_1=0.f,c12_2=0.f,c12_3=0.f, c13_0=0.f,c13_1=0.f,c13_2=0.f,c13_3=0.f;
    float c20_0=0.f,c20_1=0.f,c20_2=0.f,c20_3=0.f, c21_0=0.f,c21_1=0.f,c21_2=0.f,c21_3=0.f;
    float c22_0=0.f,c22_1=0.f,c22_2=0.f,c22_3=0.f, c23_0=0.f,c23_1=0.f,c23_2=0.f,c23_3=0.f;
    float c30_0=0.f,c30_1=0.f,c30_2=0.f,c30_3=0.f, c31_0=0.f,c31_1=0.f,c31_2=0.f,c31_3=0.f;
    float c32_0=0.f,c32_1=0.f,c32_2=0.f,c32_3=0.f, c33_0=0.f,c33_1=0.f,c33_2=0.f,c33_3=0.f;

    float4 pa0 = *(const float4*)(Ag);
    float4 pa1 = *(const float4*)(Ag + 4);
    float4 pw0 = *(const float4*)(Wg);
    float4 pw1 = *(const float4*)(Wg + 4);

// Fragment math: A(m,k): a0=(gr,gc) a1=(gr+8,gc) a2=(gr,gc+4) a3=(gr+8,gc+4)
//   A_l = float2 at row gr    -> (a0, a2);  A_h = float2 at row gr+8 -> (a1, a3)
// B(n,k): b0=(gr,gc) b1=(gr,gc+4) -> one float2.
#define GSTEP(K8) {                                                                  \
    const float2 A0l = *(const float2*)&ab[aA +        (K8)];                        \
    const float2 A0h = *(const float2*)&ab[aA + 192  + (K8)];                        \
    const float2 A1l = *(const float2*)&ab[aA + 384  + (K8)];                        \
    const float2 A1h = *(const float2*)&ab[aA + 576  + (K8)];                        \
    const float2 A2l = *(const float2*)&ab[aA + 768  + (K8)];                        \
    const float2 A2h = *(const float2*)&ab[aA + 960  + (K8)];                        \
    const float2 A3l = *(const float2*)&ab[aA + 1152 + (K8)];                        \
    const float2 A3h = *(const float2*)&ab[aA + 1344 + (K8)];                        \
    const float2 B0  = *(const float2*)&bb[bW +        (K8)];                        \
    const float2 B1  = *(const float2*)&bb[bW + 192  + (K8)];                        \
    const float2 B2  = *(const float2*)&bb[bW + 384  + (K8)];                        \
    const float2 B3  = *(const float2*)&bb[bW + 576  + (K8)];                        \
    MMA(c00_0,c00_1,c00_2,c00_3, A0l.x,A0h.x,A0l.y,A0h.y, B0.x,B0.y);                \
    MMA(c01_0,c01_1,c01_2,c01_3, A0l.x,A0h.x,A0l.y,A0h.y, B1.x,B1.y);                \
    MMA(c02_0,c02_1,c02_2,c02_3, A0l.x,A0h.x,A0l.y,A0h.y, B2.x,B2.y);                \
    MMA(c03_0,c03_1,c03_2,c03_3, A0l.x,A0h.x,A0l.y,A0h.y, B3.x,B3.y);                \
    MMA(c10_0,c10_1,c10_2,c10_3, A1l.x,A1h.x,A1l.y,A1h.y, B0.x,B0.y);                \
    MMA(c11_0,c11_1,c11_2,c11_3, A1l.x,A1h.x,A1l.y,A1h.y, B1.x,B1.y);                \
    MMA(c12_0,c12_1,c12_2,c12_3, A1l.x,A1h.x,A1l.y,A1h.y, B2.x,B2.y);                \
    MMA(c13_0,c13_1,c13_2,c13_3, A1l.x,A1h.x,A1l.y,A1h.y, B3.x,B3.y);                \
    MMA(c20_0,c20_1,c20_2,c20_3, A2l.x,A2h.x,A2l.y,A2h.y, B0.x,B0.y);                \
    MMA(c21_0,c21_1,c21_2,c21_3, A2l.x,A2h.x,A2l.y,A2h.y, B1.x,B1.y);                \
    MMA(c22_0,c22_1,c22_2,c22_3, A2l.x,A2h.x,A2l.y,A2h.y, B2.x,B2.y);                \
    MMA(c23_0,c23_1,c23_2,c23_3, A2l.x,A2h.x,A2l.y,A2h.y, B3.x,B3.y);                \
    MMA(c30_0,c30_1,c30_2,c30_3, A3l.x,A3h.x,A3l.y,A3h.y, B0.x,B0.y);                \
    MMA(c31_0,c31_1,c31_2,c31_3, A3l.x,A3h.x,A3l.y,A3h.y, B1.x,B1.y);                \
    MMA(c32_0,c32_1,c32_2,c32_3, A3l.x,A3h.x,A3l.y,A3h.y, B2.x,B2.y);                \
    MMA(c33_0,c33_1,c33_2,c33_3, A3l.x,A3h.x,A3l.y,A3h.y, B3.x,B3.y); }

#pragma unroll 1
    for (int it = 0; it < 64; ++it) {
        const int buf = it & 1;
        // permuted pair store: positions (0,1)=(k0,k4) (2,3)=(k1,k5) ...
        float* sa = As[buf] + lr * 24 + lk;
        *(float2*)&sa[0] = make_float2(tf32r(pa0.x), tf32r(pa1.x));
        *(float2*)&sa[2] = make_float2(tf32r(pa0.y), tf32r(pa1.y));
        *(float2*)&sa[4] = make_float2(tf32r(pa0.z), tf32r(pa1.z));
        *(float2*)&sa[6] = make_float2(tf32r(pa0.w), tf32r(pa1.w));
        float* sw = Ws[buf] + lr * 24 + lk;
        *(float2*)&sw[0] = make_float2(tf32r(pw0.x), tf32r(pw1.x));
        *(float2*)&sw[2] = make_float2(tf32r(pw0.y), tf32r(pw1.y));
        *(float2*)&sw[4] = make_float2(tf32r(pw0.z), tf32r(pw1.z));
        *(float2*)&sw[6] = make_float2(tf32r(pw0.w), tf32r(pw1.w));
        __syncthreads();

        if (it + 1 < 64) {
            const int k0 = (it + 1) * 16;
            pa0 = *(const float4*)(Ag + k0);
            pa1 = *(const float4*)(Ag + k0 + 4);
            pw0 = *(const float4*)(Wg + k0);
            pw1 = *(const float4*)(Wg + k0 + 4);
        }

        const float* ab = As[buf];
        const float* bb = Ws[buf];
        GSTEP(0)
        GSTEP(8)
        // next iteration writes the other buffer: no trailing sync needed
    }
#undef GSTEP

    // ---------------- epilogue (R10-proven) ----------------
#define EPI(MI, NJ, C0, C1, C2, C3) {                                                \
    const int m0 = row0 + wm*64 + (MI)*16 + gr;                                      \
    const int j  = col0 + wn*32 + (NJ)*8 + 2*gc;                                     \
    const float be = bias[j], bo = bias[j + 1];                                      \
    if (MODE == 1) {                                                                 \
        *(float2*)(C + (size_t)m0 * DIMC + j)       = make_float2((C0)+be,(C1)+bo);  \
        *(float2*)(C + (size_t)(m0 + 8) * DIMC + j) = make_float2((C2)+be,(C3)+bo);  \
    } else {                                                                         \
        const int sec   = j >> 10;                                                   \
        const int local = j & 1023;                                                  \
        const int h     = local >> 6;                                                \
        const int d     = local & 63;                                                \
        const float inv = exp2f(-(float)d * (LOG2_BASE / 64.0f));                    \
        float* basep = (sec == 0) ? g_Q : ((sec == 1) ? g_K : g_V);                  \
        {   const int m = m0;  const int b = m >> 11; const int n = m & 2047;        \
            float e = (C0) + be, o = (C1) + bo; float eo, oo;                        \
            if (sec == 2) { eo = e; oo = o; }                                        \
            else { float sv, cv; sincosf((float)n * inv, &sv, &cv);                  \
                   eo = e * cv - o * sv; oo = e * sv + o * cv;                       \
                   if (sec == 0) { eo *= 0.125f; oo *= 0.125f; } }                   \
            *(float2*)(basep + ((size_t)((b*NHEAD + h)*SEQ + n))*HD + d)             \
                = make_float2(eo, oo); }                                             \
        {   const int m = m0 + 8; const int b = m >> 11; const int n = m & 2047;     \
            float e = (C2) + be, o = (C3) + bo; float eo, oo;                        \
            if (sec == 2) { eo = e; oo = o; }                                        \
            else { float sv, cv; sincosf((float)n * inv, &sv, &cv);                  \
                   eo = e * cv - o * sv; oo = e * sv + o * cv;                       \
                   if (sec == 0) { eo *= 0.125f; oo *= 0.125f; } }                   \
            *(float2*)(basep + ((size_t)((b*NHEAD + h)*SEQ + n))*HD + d)             \
                = make_float2(eo, oo); }                                             \
    } }

    EPI(0,0, c00_0,c00_1,c00_2,c00_3)  EPI(0,1, c01_0,c01_1,c01_2,c01_3)
    EPI(0,2, c02_0,c02_1,c02_2,c02_3)  EPI(0,3, c03_0,c03_1,c03_2,c03_3)
    EPI(1,0, c10_0,c10_1,c10_2,c10_3)  EPI(1,1, c11_0,c11_1,c11_2,c11_3)
    EPI(1,2, c12_0,c12_1,c12_2,c12_3)  EPI(1,3, c13_0,c13_1,c13_2,c13_3)
    EPI(2,0, c20_0,c20_1,c20_2,c20_3)  EPI(2,1, c21_0,c21_1,c21_2,c21_3)
    EPI(2,2, c22_0,c22_1,c22_2,c22_3)  EPI(2,3, c23_0,c23_1,c23_2,c23_3)
    EPI(3,0, c30_0,c30_1,c30_2,c30_3)  EPI(3,1, c31_0,c31_1,c31_2,c31_3)
    EPI(3,2, c32_0,c32_1,c32_2,c32_3)  EPI(3,3, c33_0,c33_1,c33_2,c33_3)
#undef EPI
}

// ---------------------------------------------------------------------------
// TF32 flash attention. Block = 128 q rows x one (b,h), 256 threads (8 warps,
// 16 q-rows each) — halves K/V L2 re-read traffic vs q=64. KV tile 32.
// Q register-resident. K stored with permuted d-pairs (stride 72, LDS.64
// fragments, conflict-free); V stride 72, scalar fragment reads (R10-proven).
// smem 18.4 KB.
// ---------------------------------------------------------------------------
__global__ __launch_bounds__(256)
void tattn()
{
    __shared__ float Ks[32 * 72];
    __shared__ float Vs[32 * 72];

    const int tid  = threadIdx.x;
    const int lane = tid & 31;
    const int w    = tid >> 5;      // 0..7
    const int bh   = blockIdx.y;
    const int q0   = blockIdx.x * 128;

    const size_t base = (size_t)bh * SEQ * HD;
    const float* Qg = g_Q + base;
    const float* Kg = g_K + base;
    const float* Vg = g_V + base;

    const int gr = lane >> 2;        // 0..7
    const int gc = lane & 3;         // 0..3

    // ---- Q A-fragments, register resident (32 scalars) ----
    const float* Qb = Qg + (size_t)(q0 + w * 16 + gr) * HD + gc;
#define QLD(K8) \
    const float qa##K8##_0 = tf32r(Qb[(K8)*8]);        \
    const float qa##K8##_1 = tf32r(Qb[512 + (K8)*8]);  \
    const float qa##K8##_2 = tf32r(Qb[(K8)*8 + 4]);    \
    const float qa##K8##_3 = tf32r(Qb[512 + (K8)*8 + 4]);
    QLD(0) QLD(1) QLD(2) QLD(3) QLD(4) QLD(5) QLD(6) QLD(7)
#undef QLD

    const int kB = gr * 72 + 2 * gc; // K frag (pair-permuted): +576/nj, +8/K8
    const int vB = gc * 72 + gr;     // V frag: +576/T, +8/nj, b1 = +288
    const int s0l = (lane & ~3) | (gc >> 1);
    const int s1l = s0l + 2;
    const bool odd = (gc & 1) != 0;

    float o00=0.f,o01=0.f,o02=0.f,o03=0.f, o10=0.f,o11=0.f,o12=0.f,o13=0.f;
    float o20=0.f,o21=0.f,o22=0.f,o23=0.f, o30=0.f,o31=0.f,o32=0.f,o33=0.f;
    float o40=0.f,o41=0.f,o42=0.f,o43=0.f, o50=0.f,o51=0.f,o52=0.f,o53=0.f;
    float o60=0.f,o61=0.f,o62=0.f,o63=0.f, o70=0.f,o71=0.f,o72=0.f,o73=0.f;
    float m0 = -CUDART_INF_F, m1 = -CUDART_INF_F, l0 = 0.f, l1 = 0.f;

#define SSTEP(K8) {                                                                  \
    const float2 K0 = *(const float2*)&Ks[kB +        (K8)*8];                       \
    const float2 K1 = *(const float2*)&Ks[kB + 576  + (K8)*8];                       \
    const float2 K2 = *(const float2*)&Ks[kB + 1152 + (K8)*8];                       \
    const float2 K3 = *(const float2*)&Ks[kB + 1728 + (K8)*8];                       \
    MMA(s00,s01,s02,s03, qa##K8##_0,qa##K8##_1,qa##K8##_2,qa##K8##_3, K0.x,K0.y);    \
    MMA(s10,s11,s12,s13, qa##K8##_0,qa##K8##_1,qa##K8##_2,qa##K8##_3, K1.x,K1.y);    \
    MMA(s20,s21,s22,s23, qa##K8##_0,qa##K8##_1,qa##K8##_2,qa##K8##_3, K2.x,K2.y);    \
    MMA(s30,s31,s32,s33, qa##K8##_0,qa##K8##_1,qa##K8##_2,qa##K8##_3, K3.x,K3.y); }

#define PSTEP(T) {                                                                   \
    const float u0 = __shfl_sync(0xffffffffu, s##T##0, s0l);                         \
    const float u1 = __shfl_sync(0xffffffffu, s##T##1, s0l);                         \
    const float u2 = __shfl_sync(0xffffffffu, s##T##2, s0l);                         \
    const float u3 = __shfl_sync(0xffffffffu, s##T##3, s0l);                         \
    const float x0 = __shfl_sync(0xffffffffu, s##T##0, s1l);                         \
    const float x1 = __shfl_sync(0xffffffffu, s##T##1, s1l);                         \
    const float x2 = __shfl_sync(0xffffffffu, s##T##2, s1l);                         \
    const float x3 = __shfl_sync(0xffffffffu, s##T##3, s1l);                         \
    const float pa0 = odd ? u1 : u0;                                                 \
    const float pa1 = odd ? u3 : u2;                                                 \
    const float pa2 = odd ? x1 : x0;                                                 \
    const float pa3 = odd ? x3 : x2;                                                 \
    const int vb = vB + (T) * 576;                                                   \
    MMA(o00,o01,o02,o03, pa0,pa1,pa2,pa3, Vs[vb],    Vs[vb+288]);                    \
    MMA(o10,o11,o12,o13, pa0,pa1,pa2,pa3, Vs[vb+8],  Vs[vb+296]);                    \
    MMA(o20,o21,o22,o23, pa0,pa1,pa2,pa3, Vs[vb+16], Vs[vb+304]);                    \
    MMA(o30,o31,o32,o33, pa0,pa1,pa2,pa3, Vs[vb+24], Vs[vb+312]);                    \
    MMA(o40,o41,o42,o43, pa0,pa1,pa2,pa3, Vs[vb+32], Vs[vb+320]);                    \
    MMA(o50,o51,o52,o53, pa0,pa1,pa2,pa3, Vs[vb+40], Vs[vb+328]);                    \
    MMA(o60,o61,o62,o63, pa0,pa1,pa2,pa3, Vs[vb+48], Vs[vb+336]);                    \
    MMA(o70,o71,o72,o73, pa0,pa1,pa2,pa3, Vs[vb+56], Vs[vb+344]); }

#pragma unroll 1
    for (int kt = 0; kt < 64; ++kt) {
        const int k0 = kt * 32;
        __syncthreads();   // protect Ks/Vs from previous iteration
        for (int t = tid; t < 512; t += 256) {
            const int r = t >> 4, c = (t & 15) * 4;
            float4 kv = *(const float4*)(Kg + (size_t)(k0 + r) * HD + c);
            float4 vv = *(const float4*)(Vg + (size_t)(k0 + r) * HD + c);
            // K: permuted pair layout within each 8-d group:
            // group base (c>>3)*8, odd half (d>=4 within group) at +1, step 2
            float* dk = &Ks[r * 72 + ((c >> 3) << 3) + ((c & 4) ? 1 : 0)];
            dk[0] = tf32r(kv.x); dk[2] = tf32r(kv.y);
            dk[4] = tf32r(kv.z); dk[6] = tf32r(kv.w);
            *(float4*)&Vs[r * 72 + c] =
                make_float4(tf32r(vv.x), tf32r(vv.y), tf32r(vv.z), tf32r(vv.w));
        }
        __syncthreads();

        // ---- S = Q @ K^T ----
        float s00=0.f,s01=0.f,s02=0.f,s03=0.f, s10=0.f,s11=0.f,s12=0.f,s13=0.f;
        float s20=0.f,s21=0.f,s22=0.f,s23=0.f, s30=0.f,s31=0.f,s32=0.f,s33=0.f;
        SSTEP(0) SSTEP(1) SSTEP(2) SSTEP(3)
        SSTEP(4) SSTEP(5) SSTEP(6) SSTEP(7)

        // ---- online softmax (row gr via quad shfl 1,2) ----
        {
            float mx0 = fmaxf(fmaxf(fmaxf(s00,s01), fmaxf(s10,s11)),
                              fmaxf(fmaxf(s20,s21), fmaxf(s30,s31)));
            float mx1 = fmaxf(fmaxf(fmaxf(s02,s03), fmaxf(s12,s13)),
                              fmaxf(fmaxf(s22,s23), fmaxf(s32,s33)));
            mx0 = fmaxf(mx0, __shfl_xor_sync(0xffffffffu, mx0, 1));
            mx0 = fmaxf(mx0, __shfl_xor_sync(0xffffffffu, mx0, 2));
            mx1 = fmaxf(mx1, __shfl_xor_sync(0xffffffffu, mx1, 1));
            mx1 = fmaxf(mx1, __shfl_xor_sync(0xffffffffu, mx1, 2));
            const float mn0 = fmaxf(m0, mx0);
            const float mn1 = fmaxf(m1, mx1);
            const float al0 = __expf(m0 - mn0);
            const float al1 = __expf(m1 - mn1);
            s00=tf32r(__expf(s00-mn0)); s01=tf32r(__expf(s01-mn0));
            s10=tf32r(__expf(s10-mn0)); s11=tf32r(__expf(s11-mn0));
            s20=tf32r(__expf(s20-mn0)); s21=tf32r(__expf(s21-mn0));
            s30=tf32r(__expf(s30-mn0)); s31=tf32r(__expf(s31-mn0));
            s02=tf32r(__expf(s02-mn1)); s03=tf32r(__expf(s03-mn1));
            s12=tf32r(__expf(s12-mn1)); s13=tf32r(__expf(s13-mn1));
            s22=tf32r(__expf(s22-mn1)); s23=tf32r(__expf(s23-mn1));
            s32=tf32r(__expf(s32-mn1)); s33=tf32r(__expf(s33-mn1));
            float sum0 = ((s00+s01)+(s10+s11)) + ((s20+s21)+(s30+s31));
            float sum1 = ((s02+s03)+(s12+s13)) + ((s22+s23)+(s32+s33));
            sum0 += __shfl_xor_sync(0xffffffffu, sum0, 1);
            sum0 += __shfl_xor_sync(0xffffffffu, sum0, 2);
            sum1 += __shfl_xor_sync(0xffffffffu, sum1, 1);
            sum1 += __shfl_xor_sync(0xffffffffu, sum1, 2);
            l0 = l0 * al0 + sum0;  m0 = mn0;
            l1 = l1 * al1 + sum1;  m1 = mn1;
            o00*=al0; o01*=al0; o10*=al0; o11*=al0; o20*=al0; o21*=al0; o30*=al0; o31*=al0;
            o40*=al0; o41*=al0; o50*=al0; o51*=al0; o60*=al0; o61*=al0; o70*=al0; o71*=al0;
            o02*=al1; o03*=al1; o12*=al1; o13*=al1; o22*=al1; o23*=al1; o32*=al1; o33*=al1;
            o42*=al1; o43*=al1; o52*=al1; o53*=al1; o62*=al1; o63*=al1; o72*=al1; o73*=al1;
        }

        // ---- O += P @ V ----
        PSTEP(0) PSTEP(1) PSTEP(2) PSTEP(3)
    }
#undef SSTEP
#undef PSTEP

    // ---- normalize + write O to g_O [B,N,1024] ----
    {
        const float il0 = 1.f / l0;
        const float il1 = 1.f / l1;
        const int b = bh >> 4;
        const int h = bh & 15;
        const int n = q0 + w * 16 + gr;
        float* O0 = g_O + ((size_t)(b * SEQ + n)) * DIMC + h * HD + 2 * gc;
        float* O1 = O0 + (size_t)8 * DIMC;
        *(float2*)(O0 + 0)  = make_float2(o00*il0, o01*il0);
        *(float2*)(O0 + 8)  = make_float2(o10*il0, o11*il0);
        *(float2*)(O0 + 16) = make_float2(o20*il0, o21*il0);
        *(float2*)(O0 + 24) = make_float2(o30*il0, o31*il0);
        *(float2*)(O0 + 32) = make_float2(o40*il0, o41*il0);
        *(float2*)(O0 + 40) = make_float2(o50*il0, o51*il0);
        *(float2*)(O0 + 48) = make_float2(o60*il0, o61*il0);
        *(float2*)(O0 + 56) = make_float2(o70*il0, o71*il0);
        *(float2*)(O1 + 0)  = make_float2(o02*il1, o03*il1);
        *(float2*)(O1 + 8)  = make_float2(o12*il1, o13*il1);
        *(float2*)(O1 + 16) = make_float2(o22*il1, o23*il1);
        *(float2*)(O1 + 24) = make_float2(o32*il1, o33*il1);
        *(float2*)(O1 + 32) = make_float2(o42*il1, o43*il1);
        *(float2*)(O1 + 40) = make_float2(o52*il1, o53*il1);
        *(float2*)(O1 + 48) = make_float2(o62*il1, o63*il1);
        *(float2*)(O1 + 56) = make_float2(o72*il1, o73*il1);
    }
}

// ---------------------------------------------------------------------------

extern "C" void kernel_launch(void* const* d_in, const int* in_sizes, int n_in,
                              void* d_out, int out_size)
{
    const float* x      = (const float*)d_in[0];
    const float* qkv_w  = (const float*)d_in[1];
    const float* qkv_b  = (const float*)d_in[2];
    const float* proj_w = (const float*)d_in[3];
    const float* proj_b = (const float*)d_in[4];
    float* out = (float*)d_out;

    tgemm<0><<<dim3(QKVN / 128, MTOT / 128), 256>>>(x, qkv_w, qkv_b, nullptr);
    tattn<<<dim3(SEQ / 128, BATCH * NHEAD), 256>>>();
    tgemm<1><<<dim3(DIMC / 128, MTOT / 128), 256>>>(nullptr, proj_w, proj_b, out);
}